// round 3
// baseline (speedup 1.0000x reference)
#include <cuda_runtime.h>

#define NB 64
#define NT 512
#define ND 512
#define NI 1024
#define NG 2048
#define NCTA 128

__device__ __align__(16) float g_xw1[(size_t)NB * NT * NG];
__device__ __align__(16) float g_xwf[(size_t)NB * NT * NG];
__device__ __align__(16) float g_xwb[(size_t)NB * NT * NG];
__device__ __align__(16) float g_h1 [(size_t)NB * NT * ND];
__device__ __align__(16) float g_hf [(size_t)NB * NT * ND];
__device__ __align__(16) float g_hb [(size_t)NB * NT * ND];
__device__ unsigned g_bar1;
__device__ unsigned g_bar2;

// ---------- packed f32x2 (FFMA2: 2x scalar FFMA throughput on sm_103a) ----------
__device__ __forceinline__ unsigned long long pack2(float lo, float hi) {
    unsigned long long v;
    asm("mov.b64 %0, {%1, %2};" : "=l"(v) : "f"(lo), "f"(hi));
    return v;
}
__device__ __forceinline__ float2 unpack2(unsigned long long v) {
    float lo, hi;
    asm("mov.b64 {%0, %1}, %2;" : "=f"(lo), "=f"(hi) : "l"(v));
    return make_float2(lo, hi);
}
__device__ __forceinline__ void ffma2(unsigned long long& c, unsigned long long a, unsigned long long b) {
    asm("fma.rn.f32x2 %0, %1, %2, %0;" : "+l"(c) : "l"(a), "l"(b));
}
__device__ __forceinline__ float sigm(float z) { return 1.f / (1.f + __expf(-z)); }

// ---------- grid-wide spin barrier (monotonic counter, reset each launch) ----------
__device__ __forceinline__ void grid_barrier(unsigned* bar, unsigned target) {
    __threadfence();
    __syncthreads();
    if (threadIdx.x == 0) {
        atomicAdd(bar, 1u);
        while (*((volatile unsigned*)bar) < target) __nanosleep(64);
        __threadfence();
    }
    __syncthreads();
}

__global__ void reset_bars_kernel() { g_bar1 = 0u; g_bar2 = 0u; }

// ---------- SGEMM: C[M,N] = A[M,K] @ W[K,N] + bias ----------
#define GBM 128
#define GBN 128
#define GBK 16

__global__ __launch_bounds__(256, 1) void sgemm_bias_kernel(
    const float* __restrict__ A, const float* __restrict__ W,
    const float* __restrict__ bias, float* __restrict__ C,
    int M, int N, int K)
{
    __shared__ __align__(16) float As[GBK][GBM + 4];
    __shared__ __align__(16) float Bs[GBK][GBN + 4];

    const int tid = threadIdx.x;
    const int n0 = blockIdx.x * GBN;
    const int m0 = blockIdx.y * GBM;
    const int tx = tid & 15;
    const int ty = tid >> 4;

    unsigned long long acc[8][4];
#pragma unroll
    for (int i = 0; i < 8; ++i)
#pragma unroll
        for (int j = 0; j < 4; ++j) acc[i][j] = 0ull;

    for (int k0 = 0; k0 < K; k0 += GBK) {
#pragma unroll
        for (int i = 0; i < 2; ++i) {
            int idx = i * 256 + tid;
            int row = idx >> 2;
            int c4 = (idx & 3) << 2;
            float4 av = *(const float4*)&A[(size_t)(m0 + row) * K + k0 + c4];
            As[c4 + 0][row] = av.x; As[c4 + 1][row] = av.y;
            As[c4 + 2][row] = av.z; As[c4 + 3][row] = av.w;
        }
#pragma unroll
        for (int i = 0; i < 2; ++i) {
            int idx = i * 256 + tid;
            int r = idx >> 5;
            int c4 = (idx & 31) << 2;
            *(float4*)&Bs[r][c4] = *(const float4*)&W[(size_t)(k0 + r) * N + n0 + c4];
        }
        __syncthreads();

#pragma unroll
        for (int k = 0; k < GBK; ++k) {
            float4 a0 = *(float4*)&As[k][ty * 4];
            float4 a1 = *(float4*)&As[k][64 + ty * 4];
            float4 b0 = *(float4*)&Bs[k][tx * 4];
            float4 b1 = *(float4*)&Bs[k][64 + tx * 4];
            float ra[8] = {a0.x, a0.y, a0.z, a0.w, a1.x, a1.y, a1.z, a1.w};
            unsigned long long bp[4] = {pack2(b0.x, b0.y), pack2(b0.z, b0.w),
                                        pack2(b1.x, b1.y), pack2(b1.z, b1.w)};
#pragma unroll
            for (int i = 0; i < 8; ++i) {
                unsigned long long a2 = pack2(ra[i], ra[i]);
#pragma unroll
                for (int j = 0; j < 4; ++j) ffma2(acc[i][j], a2, bp[j]);
            }
        }
        __syncthreads();
    }

    float4 bv0 = *(const float4*)&bias[n0 + tx * 4];
    float4 bv1 = *(const float4*)&bias[n0 + 64 + tx * 4];
#pragma unroll
    for (int i = 0; i < 8; ++i) {
        int row = (i < 4) ? (ty * 4 + i) : (64 + ty * 4 + (i - 4));
        float* cp = &C[(size_t)(m0 + row) * N + n0];
        float2 a0 = unpack2(acc[i][0]), a1 = unpack2(acc[i][1]);
        float2 a2 = unpack2(acc[i][2]), a3 = unpack2(acc[i][3]);
        float4 o0 = make_float4(a0.x + bv0.x, a0.y + bv0.y, a1.x + bv0.z, a1.y + bv0.w);
        float4 o1 = make_float4(a2.x + bv1.x, a2.y + bv1.y, a3.x + bv1.z, a3.y + bv1.w);
        *(float4*)&cp[tx * 4] = o0;
        *(float4*)&cp[64 + tx * 4] = o1;
    }
}

// ---------- LSTM recurrence pieces ----------
// tid = uu*64 + b. CTA owns units u0..u0+3. Us[k*16 + uu*4 + g].
__device__ __forceinline__ void lstm_accum(
    const float* __restrict__ harr, int tprev,
    const float* __restrict__ Us, float* __restrict__ hsrc,
    unsigned long long& acc01, unsigned long long& acc23,
    int tid, int uu, int b)
{
    for (int kc = 0; kc < 8; ++kc) {
        __syncthreads();
#pragma unroll
        for (int i = 0; i < 4; ++i) {
            int idx = i * 256 + tid;
            int bb = idx >> 4;
            int kk4 = (idx & 15) << 2;
            float4 hv4 = *(const float4*)&harr[((size_t)bb * NT + tprev) * ND + kc * 64 + kk4];
            hsrc[(kk4 + 0) * 65 + bb] = hv4.x;
            hsrc[(kk4 + 1) * 65 + bb] = hv4.y;
            hsrc[(kk4 + 2) * 65 + bb] = hv4.z;
            hsrc[(kk4 + 3) * 65 + bb] = hv4.w;
        }
        __syncthreads();
#pragma unroll
        for (int kk = 0; kk < 64; ++kk) {
            float hv = hsrc[kk * 65 + b];
            float4 u4 = *(const float4*)&Us[(kc * 64 + kk) * 16 + (uu << 2)];
            unsigned long long a2 = pack2(hv, hv);
            ffma2(acc01, a2, pack2(u4.x, u4.y));
            ffma2(acc23, a2, pack2(u4.z, u4.w));
        }
    }
}

__device__ __forceinline__ void lstm_gate(
    const float* __restrict__ xw, float* __restrict__ hout,
    int t, int u0,
    unsigned long long acc01, unsigned long long acc23,
    float& c, float* __restrict__ zs, float* __restrict__ shs,
    int tid, int uu, int b)
{
    __syncthreads();
    {
        int bb = tid >> 2, g = tid & 3;
        float4 xv = *(const float4*)&xw[((size_t)bb * NT + t) * NG + (size_t)g * ND + u0];
        *(float4*)&zs[bb * 20 + (g << 2)] = xv;
    }
    __syncthreads();
    float2 a01 = unpack2(acc01), a23 = unpack2(acc23);
    float zi = zs[b * 20 + uu]      + a01.x;
    float zf = zs[b * 20 + 4 + uu]  + a01.y;
    float zg = zs[b * 20 + 8 + uu]  + a23.x;
    float zo = zs[b * 20 + 12 + uu] + a23.y;
    float ig = sigm(zi), fg = sigm(zf);
    float gv = fmaxf(zg, 0.f), og = sigm(zo);
    c = fmaf(fg, c, ig * gv);
    float h = og * fmaxf(c, 0.f);
    shs[(b << 2) + uu] = h;
    __syncthreads();
    if (tid < 64) {
        float4 h4 = *(float4*)&shs[tid << 2];
        *(float4*)&hout[((size_t)tid * NT + t) * ND + u0] = h4;
    }
}

// ---------- LSTM1 persistent kernel ----------
__global__ __launch_bounds__(256) void lstm1_kernel(const float* __restrict__ U)
{
    extern __shared__ float sm[];
    float* Us   = sm;                 // 8192
    float* hsrc = sm + 8192;          // 4160
    float* zs   = sm + 12352;         // 1280
    float* shs  = sm + 13632;         // 256

    const int tid = threadIdx.x;
    const int uu = tid >> 6, b = tid & 63;
    const int u0 = blockIdx.x << 2;

    for (int idx = tid; idx < 8192; idx += 256) {
        int k = idx >> 4, j = idx & 15;
        Us[idx] = U[(size_t)k * NG + (size_t)(j & 3) * ND + u0 + (j >> 2)];
    }
    __syncthreads();

    float c = 0.f;
    for (int t = 0; t < NT; ++t) {
        unsigned long long acc01 = 0ull, acc23 = 0ull;
        if (t > 0) {
            grid_barrier(&g_bar1, (unsigned)t * NCTA);
            lstm_accum(g_h1, t - 1, Us, hsrc, acc01, acc23, tid, uu, b);
        }
        lstm_gate(g_xw1, g_h1, t, u0, acc01, acc23, c, zs, shs, tid, uu, b);
    }
}

// ---------- fused forward+backward LSTM persistent kernel ----------
__global__ __launch_bounds__(256) void lstmfb_kernel(
    const float* __restrict__ Uf, const float* __restrict__ Ub)
{
    extern __shared__ float sm[];
    float* Ufs  = sm;                  // 8192
    float* Ubs  = sm + 8192;           // 8192
    float* hsrc = sm + 16384;          // 4160
    float* zs   = sm + 20544;          // 1280
    float* shs  = sm + 21824;          // 256

    const int tid = threadIdx.x;
    const int uu = tid >> 6, b = tid & 63;
    const int u0 = blockIdx.x << 2;

    for (int idx = tid; idx < 8192; idx += 256) {
        int k = idx >> 4, j = idx & 15;
        size_t gi = (size_t)k * NG + (size_t)(j & 3) * ND + u0 + (j >> 2);
        Ufs[idx] = Uf[gi];
        Ubs[idx] = Ub[gi];
    }
    __syncthreads();

    float cf = 0.f, cb = 0.f;
    for (int s = 0; s < NT; ++s) {
        int tf = s, tb = NT - 1 - s;
        unsigned long long af01 = 0ull, af23 = 0ull, ab01 = 0ull, ab23 = 0ull;
        if (s > 0) {
            grid_barrier(&g_bar2, (unsigned)s * NCTA);
            lstm_accum(g_hf, tf - 1, Ufs, hsrc, af01, af23, tid, uu, b);
            lstm_accum(g_hb, tb + 1, Ubs, hsrc, ab01, ab23, tid, uu, b);
        }
        lstm_gate(g_xwf, g_hf, tf, u0, af01, af23, cf, zs, shs, tid, uu, b);
        lstm_gate(g_xwb, g_hb, tb, u0, ab01, ab23, cb, zs, shs, tid, uu, b);
    }
}

// ---------- LayerNorm(concat(hf,hb)) * gamma + beta + x ----------
__global__ __launch_bounds__(256) void ln_kernel(
    const float* __restrict__ x, const float* __restrict__ gamma,
    const float* __restrict__ beta, float* __restrict__ out)
{
    __shared__ float red[16];
    __shared__ float s_mu, s_rs;
    const int r = blockIdx.x;
    const int tid = threadIdx.x;

    float4 v;
    if (tid < 128) v = *(const float4*)&g_hf[(size_t)r * ND + (tid << 2)];
    else           v = *(const float4*)&g_hb[(size_t)r * ND + ((tid - 128) << 2)];

    float s = v.x + v.y + v.z + v.w;
    float q = v.x * v.x + v.y * v.y + v.z * v.z + v.w * v.w;
#pragma unroll
    for (int o = 16; o; o >>= 1) {
        s += __shfl_down_sync(0xffffffffu, s, o);
        q += __shfl_down_sync(0xffffffffu, q, o);
    }
    if ((tid & 31) == 0) { red[tid >> 5] = s; red[8 + (tid >> 5)] = q; }
    __syncthreads();
    if (tid == 0) {
        float S = 0.f, Q = 0.f;
#pragma unroll
        for (int i = 0; i < 8; ++i) { S += red[i]; Q += red[8 + i]; }
        float mu = S * (1.f / 1024.f);
        float var = Q * (1.f / 1024.f) - mu * mu;
        s_mu = mu;
        s_rs = rsqrtf(var + 1e-6f);
    }
    __syncthreads();
    float mu = s_mu, rs = s_rs;
    int col = tid << 2;
    float4 g4 = *(const float4*)&gamma[col];
    float4 b4 = *(const float4*)&beta[col];
    float4 xv = *(const float4*)&x[(size_t)r * NI + col];
    float4 o;
    o.x = xv.x + (v.x - mu) * rs * g4.x + b4.x;
    o.y = xv.y + (v.y - mu) * rs * g4.y + b4.y;
    o.z = xv.z + (v.z - mu) * rs * g4.z + b4.z;
    o.w = xv.w + (v.w - mu) * rs * g4.w + b4.w;
    *(float4*)&out[(size_t)r * NI + col] = o;
}

// ---------- host launch ----------
#define SMEM_L1 (13888 * 4)
#define SMEM_FB (22080 * 4)

extern "C" void kernel_launch(void* const* d_in, const int* in_sizes, int n_in,
                              void* d_out, int out_size)
{
    const float* x     = (const float*)d_in[0];
    const float* W1    = (const float*)d_in[1];
    const float* U1    = (const float*)d_in[2];
    const float* b1    = (const float*)d_in[3];
    const float* Wf    = (const float*)d_in[4];
    const float* Uf    = (const float*)d_in[5];
    const float* bf    = (const float*)d_in[6];
    const float* Wb    = (const float*)d_in[7];
    const float* Ub    = (const float*)d_in[8];
    const float* bb    = (const float*)d_in[9];
    const float* gamma = (const float*)d_in[10];
    const float* beta  = (const float*)d_in[11];
    float* out = (float*)d_out;

    void *p_xw1, *p_xwf, *p_xwb, *p_h1;
    cudaGetSymbolAddress(&p_xw1, g_xw1);
    cudaGetSymbolAddress(&p_xwf, g_xwf);
    cudaGetSymbolAddress(&p_xwb, g_xwb);
    cudaGetSymbolAddress(&p_h1,  g_h1);

    cudaFuncSetAttribute(lstm1_kernel,  cudaFuncAttributeMaxDynamicSharedMemorySize, SMEM_L1);
    cudaFuncSetAttribute(lstmfb_kernel, cudaFuncAttributeMaxDynamicSharedMemorySize, SMEM_FB);

    const int M = NB * NT;
    dim3 gg(NG / GBN, M / GBM);

    reset_bars_kernel<<<1, 1>>>();
    sgemm_bias_kernel<<<gg, 256>>>(x, W1, b1, (float*)p_xw1, M, NG, NI);
    lstm1_kernel<<<NCTA, 256, SMEM_L1>>>(U1);
    sgemm_bias_kernel<<<gg, 256>>>((const float*)p_h1, Wf, bf, (float*)p_xwf, M, NG, ND);
    sgemm_bias_kernel<<<gg, 256>>>((const float*)p_h1, Wb, bb, (float*)p_xwb, M, NG, ND);
    lstmfb_kernel<<<NCTA, 256, SMEM_FB>>>(Uf, Ub);
    ln_kernel<<<M, 256>>>(x, gamma, beta, out);
}

// round 4
// speedup vs baseline: 1.1901x; 1.1901x over previous
#include <cuda_runtime.h>

#define NB 64
#define NT 512
#define ND 512
#define NI 1024
#define NG 2048
#define NCTA 128

typedef unsigned long long ull;

__device__ __align__(16) float g_xw1[(size_t)NB * NT * NG];
__device__ __align__(16) float g_xwf[(size_t)NB * NT * NG];
__device__ __align__(16) float g_xwb[(size_t)NB * NT * NG];
__device__ __align__(16) float g_h1 [(size_t)NB * NT * ND];
__device__ __align__(16) float g_hf [(size_t)NB * NT * ND];
__device__ __align__(16) float g_hb [(size_t)NB * NT * ND];
__device__ unsigned g_bar1;
__device__ unsigned g_bar2;

// ---------- packed f32x2 ----------
__device__ __forceinline__ ull pack2(float lo, float hi) {
    ull v; asm("mov.b64 %0, {%1, %2};" : "=l"(v) : "f"(lo), "f"(hi)); return v;
}
__device__ __forceinline__ float2 unpack2(ull v) {
    float lo, hi; asm("mov.b64 {%0, %1}, %2;" : "=f"(lo), "=f"(hi) : "l"(v));
    return make_float2(lo, hi);
}
__device__ __forceinline__ void ffma2(ull& c, ull a, ull b) {
    asm("fma.rn.f32x2 %0, %1, %2, %0;" : "+l"(c) : "l"(a), "l"(b));
}
__device__ __forceinline__ float sigm(float z) { return 1.f / (1.f + __expf(-z)); }

// ---------- grid-wide spin barrier ----------
__device__ __forceinline__ void grid_barrier(unsigned* bar, unsigned target) {
    __threadfence();
    __syncthreads();
    if (threadIdx.x == 0) {
        atomicAdd(bar, 1u);
        while (*((volatile unsigned*)bar) < target) { }
        __threadfence();
    }
    __syncthreads();
}

__global__ void reset_bars_kernel() { g_bar1 = 0u; g_bar2 = 0u; }

// ---------- SGEMM (unchanged from R2: near FFMA2 roofline) ----------
#define GBM 128
#define GBN 128
#define GBK 16

__global__ __launch_bounds__(256, 1) void sgemm_bias_kernel(
    const float* __restrict__ A, const float* __restrict__ W,
    const float* __restrict__ bias, float* __restrict__ C,
    int M, int N, int K)
{
    __shared__ __align__(16) float As[GBK][GBM + 4];
    __shared__ __align__(16) float Bs[GBK][GBN + 4];

    const int tid = threadIdx.x;
    const int n0 = blockIdx.x * GBN;
    const int m0 = blockIdx.y * GBM;
    const int tx = tid & 15;
    const int ty = tid >> 4;

    ull acc[8][4];
#pragma unroll
    for (int i = 0; i < 8; ++i)
#pragma unroll
        for (int j = 0; j < 4; ++j) acc[i][j] = 0ull;

    for (int k0 = 0; k0 < K; k0 += GBK) {
#pragma unroll
        for (int i = 0; i < 2; ++i) {
            int idx = i * 256 + tid;
            int row = idx >> 2;
            int c4 = (idx & 3) << 2;
            float4 av = *(const float4*)&A[(size_t)(m0 + row) * K + k0 + c4];
            As[c4 + 0][row] = av.x; As[c4 + 1][row] = av.y;
            As[c4 + 2][row] = av.z; As[c4 + 3][row] = av.w;
        }
#pragma unroll
        for (int i = 0; i < 2; ++i) {
            int idx = i * 256 + tid;
            int r = idx >> 5;
            int c4 = (idx & 31) << 2;
            *(float4*)&Bs[r][c4] = *(const float4*)&W[(size_t)(k0 + r) * N + n0 + c4];
        }
        __syncthreads();

#pragma unroll
        for (int k = 0; k < GBK; ++k) {
            float4 a0 = *(float4*)&As[k][ty * 4];
            float4 a1 = *(float4*)&As[k][64 + ty * 4];
            float4 b0 = *(float4*)&Bs[k][tx * 4];
            float4 b1 = *(float4*)&Bs[k][64 + tx * 4];
            float ra[8] = {a0.x, a0.y, a0.z, a0.w, a1.x, a1.y, a1.z, a1.w};
            ull bp[4] = {pack2(b0.x, b0.y), pack2(b0.z, b0.w),
                         pack2(b1.x, b1.y), pack2(b1.z, b1.w)};
#pragma unroll
            for (int i = 0; i < 8; ++i) {
                ull a2 = pack2(ra[i], ra[i]);
#pragma unroll
                for (int j = 0; j < 4; ++j) ffma2(acc[i][j], a2, bp[j]);
            }
        }
        __syncthreads();
    }

    float4 bv0 = *(const float4*)&bias[n0 + tx * 4];
    float4 bv1 = *(const float4*)&bias[n0 + 64 + tx * 4];
#pragma unroll
    for (int i = 0; i < 8; ++i) {
        int row = (i < 4) ? (ty * 4 + i) : (64 + ty * 4 + (i - 4));
        float* cp = &C[(size_t)(m0 + row) * N + n0];
        float2 a0 = unpack2(acc[i][0]), a1 = unpack2(acc[i][1]);
        float2 a2 = unpack2(acc[i][2]), a3 = unpack2(acc[i][3]);
        float4 o0 = make_float4(a0.x + bv0.x, a0.y + bv0.y, a1.x + bv0.z, a1.y + bv0.w);
        float4 o1 = make_float4(a2.x + bv1.x, a2.y + bv1.y, a3.x + bv1.z, a3.y + bv1.w);
        *(float4*)&cp[tx * 4] = o0;
        *(float4*)&cp[64 + tx * 4] = o1;
    }
}

// ================= LSTM recurrence (new: k-split, packed-U, double-buffered) =================
// 256 threads: tid = kh*128 + up*64 + b.  kh: k-half (even/odd kk), up: unit-pair,
// b: batch. CTA owns units u0..u0+3 (u0 = blockIdx.x*4). Each thread accumulates
// 2 units x 4 gates over half of k; partials combined via shared scratch.
// Us layout (packed for ulonglong2 loads): Us[k*16 + up*8 + sel*4 + g]  (g: i,f,g,o)

__device__ __forceinline__ void load_U_shared(float* Us, const float* __restrict__ U,
                                              int u0, int tid) {
    for (int idx = tid; idx < 8192; idx += 256) {
        int k = idx >> 4, r = idx & 15;
        int up_ = r >> 3, sel = (r >> 2) & 1, g = r & 3;
        Us[idx] = U[(size_t)k * NG + (size_t)g * ND + u0 + up_ * 2 + sel];
    }
}

__device__ __forceinline__ void stage_load(float4* r, const float* __restrict__ harr,
                                           int tprev, int kc, int tid) {
#pragma unroll
    for (int i = 0; i < 4; ++i) {
        int idx = i * 256 + tid;
        int bb = idx >> 4;
        int kk4 = (idx & 15) << 2;
        r[i] = *(const float4*)&harr[((size_t)bb * NT + tprev) * ND + kc * 64 + kk4];
    }
}

__device__ __forceinline__ void stage_store(float* hbuf, const float4* r, int tid) {
#pragma unroll
    for (int i = 0; i < 4; ++i) {
        int idx = i * 256 + tid;
        int bb = idx >> 4;
        int kk4 = (idx & 15) << 2;
        hbuf[(kk4 + 0) * 65 + bb] = r[i].x;
        hbuf[(kk4 + 1) * 65 + bb] = r[i].y;
        hbuf[(kk4 + 2) * 65 + bb] = r[i].z;
        hbuf[(kk4 + 3) * 65 + bb] = r[i].w;
    }
}

__device__ __forceinline__ void compute_chunk(
    const float* hc, const float* Us, int kc, int b, int up, int kh,
    ull& aA01, ull& aA23, ull& aB01, ull& aB23)
{
#pragma unroll
    for (int j = 0; j < 32; ++j) {
        int kk = (j << 1) | kh;
        float hv = hc[kk * 65 + b];
        ull a2 = pack2(hv, hv);
        const ulonglong2* up8 =
            (const ulonglong2*)&Us[((kc << 6) + kk) * 16 + (up << 3)];
        ulonglong2 uA = up8[0];
        ulonglong2 uB = up8[1];
        ffma2(aA01, a2, uA.x); ffma2(aA23, a2, uA.y);
        ffma2(aB01, a2, uB.x); ffma2(aB23, a2, uB.y);
    }
}

__device__ __forceinline__ void accum_h(
    const float* __restrict__ harr, int tprev, const float* Us,
    float* hA, float* hB, int tid, int b, int up, int kh,
    ull& a0, ull& a1, ull& a2, ull& a3)
{
    float4 r[4];
    stage_load(r, harr, tprev, 0, tid);
    stage_store(hA, r, tid);
    __syncthreads();
#pragma unroll 1
    for (int kc = 0; kc < 8; ++kc) {
        float* cur = (kc & 1) ? hB : hA;
        float* nxt = (kc & 1) ? hA : hB;
        if (kc < 7) stage_load(r, harr, tprev, kc + 1, tid);
        compute_chunk(cur, Us, kc, b, up, kh, a0, a1, a2, a3);
        if (kc < 7) stage_store(nxt, r, tid);
        __syncthreads();
    }
}

__device__ __forceinline__ void stage_zs(float* zs, const float* __restrict__ xw,
                                         int t, int u0, int tid) {
    int bb = tid >> 2, g = tid & 3;
    float4 xv = *(const float4*)&xw[((size_t)bb * NT + t) * NG + (size_t)g * ND + u0];
    *(float4*)&zs[bb * 20 + (g << 2)] = xv;
}

__device__ __forceinline__ void gate_apply(
    float* __restrict__ hout, int t, int u0, const float* zs, float* scr_f,
    ull aA01, ull aA23, ull aB01, ull aB23,
    float& cA, float& cB, float* shs, int tid, int b, int up, int kh)
{
    ull* s = (ull*)scr_f;
    int w = (up << 6) + b;
    if (kh) {
        s[w * 4 + 0] = aA01; s[w * 4 + 1] = aA23;
        s[w * 4 + 2] = aB01; s[w * 4 + 3] = aB23;
    }
    __syncthreads();
    if (!kh) {
        float2 pa = unpack2(s[w * 4 + 0]), pb = unpack2(s[w * 4 + 1]);
        float2 pc = unpack2(s[w * 4 + 2]), pd = unpack2(s[w * 4 + 3]);
        float2 aA = unpack2(aA01), aB = unpack2(aA23);
        float2 aC = unpack2(aB01), aD = unpack2(aB23);
        int uA = (up << 1), uB = uA + 1;
        const float* z = zs + b * 20;
        float ziA = z[uA]      + aA.x + pa.x;
        float zfA = z[4 + uA]  + aA.y + pa.y;
        float zgA = z[8 + uA]  + aB.x + pb.x;
        float zoA = z[12 + uA] + aB.y + pb.y;
        float ziB = z[uB]      + aC.x + pc.x;
        float zfB = z[4 + uB]  + aC.y + pc.y;
        float zgB = z[8 + uB]  + aD.x + pd.x;
        float zoB = z[12 + uB] + aD.y + pd.y;
        cA = fmaf(sigm(zfA), cA, sigm(ziA) * fmaxf(zgA, 0.f));
        float hA_ = sigm(zoA) * fmaxf(cA, 0.f);
        cB = fmaf(sigm(zfB), cB, sigm(ziB) * fmaxf(zgB, 0.f));
        float hB_ = sigm(zoB) * fmaxf(cB, 0.f);
        shs[(b << 2) + uA] = hA_;
        shs[(b << 2) + uB] = hB_;
    }
    __syncthreads();
    if (tid < 64) {
        float4 h4 = *(float4*)&shs[tid << 2];
        *(float4*)&hout[((size_t)tid * NT + t) * ND + u0] = h4;
    }
}

// ---------- LSTM1 persistent kernel ----------
// smem floats: Us 8192 | hA 4160 | hB 4160 | zs 1280 | scr 1024 | shs 256 = 19072
#define SMEM_L1 (19072 * 4)

__global__ __launch_bounds__(256) void lstm1_kernel(const float* __restrict__ U)
{
    extern __shared__ float sm[];
    float* Us  = sm;
    float* hA  = sm + 8192;
    float* hB  = sm + 12352;
    float* zs  = sm + 16512;
    float* scr = sm + 17792;
    float* shs = sm + 18816;

    const int tid = threadIdx.x;
    const int kh = tid >> 7;
    const int up = (tid >> 6) & 1;
    const int b  = tid & 63;
    const int u0 = blockIdx.x << 2;

    load_U_shared(Us, U, u0, tid);
    __syncthreads();

    float cA = 0.f, cB = 0.f;
    for (int t = 0; t < NT; ++t) {
        stage_zs(zs, g_xw1, t, u0, tid);
        ull a0 = 0ull, a1 = 0ull, a2 = 0ull, a3 = 0ull;
        if (t > 0) {
            grid_barrier(&g_bar1, (unsigned)t * NCTA);
            accum_h(g_h1, t - 1, Us, hA, hB, tid, b, up, kh, a0, a1, a2, a3);
        } else {
            __syncthreads();
        }
        gate_apply(g_h1, t, u0, zs, scr, a0, a1, a2, a3, cA, cB, shs, tid, b, up, kh);
    }
}

// ---------- fused forward+backward LSTM persistent kernel ----------
// smem floats: Ufs 8192 | Ubs 8192 | hA 4160 | hB 4160 | zsf 1280 | zsb 1280 | scr 1024 | shs 256 = 28544
#define SMEM_FB (28544 * 4)

__global__ __launch_bounds__(256) void lstmfb_kernel(
    const float* __restrict__ Uf, const float* __restrict__ Ub)
{
    extern __shared__ float sm[];
    float* Ufs = sm;
    float* Ubs = sm + 8192;
    float* hA  = sm + 16384;
    float* hB  = sm + 20544;
    float* zsf = sm + 24704;
    float* zsb = sm + 25984;
    float* scr = sm + 27264;
    float* shs = sm + 28288;

    const int tid = threadIdx.x;
    const int kh = tid >> 7;
    const int up = (tid >> 6) & 1;
    const int b  = tid & 63;
    const int u0 = blockIdx.x << 2;

    load_U_shared(Ufs, Uf, u0, tid);
    load_U_shared(Ubs, Ub, u0, tid);
    __syncthreads();

    float cfA = 0.f, cfB = 0.f, cbA = 0.f, cbB = 0.f;
    for (int s = 0; s < NT; ++s) {
        int tf = s, tb = NT - 1 - s;
        stage_zs(zsf, g_xwf, tf, u0, tid);
        stage_zs(zsb, g_xwb, tb, u0, tid);
        ull f0 = 0ull, f1 = 0ull, f2 = 0ull, f3 = 0ull;
        ull r0 = 0ull, r1 = 0ull, r2 = 0ull, r3 = 0ull;
        if (s > 0) {
            grid_barrier(&g_bar2, (unsigned)s * NCTA);
            accum_h(g_hf, tf - 1, Ufs, hA, hB, tid, b, up, kh, f0, f1, f2, f3);
            accum_h(g_hb, tb + 1, Ubs, hA, hB, tid, b, up, kh, r0, r1, r2, r3);
        } else {
            __syncthreads();
        }
        gate_apply(g_hf, tf, u0, zsf, scr, f0, f1, f2, f3, cfA, cfB, shs, tid, b, up, kh);
        gate_apply(g_hb, tb, u0, zsb, scr, r0, r1, r2, r3, cbA, cbB, shs, tid, b, up, kh);
    }
}

// ---------- LayerNorm(concat(hf,hb)) * gamma + beta + x ----------
__global__ __launch_bounds__(256) void ln_kernel(
    const float* __restrict__ x, const float* __restrict__ gamma,
    const float* __restrict__ beta, float* __restrict__ out)
{
    __shared__ float red[16];
    __shared__ float s_mu, s_rs;
    const int r = blockIdx.x;
    const int tid = threadIdx.x;

    float4 v;
    if (tid < 128) v = *(const float4*)&g_hf[(size_t)r * ND + (tid << 2)];
    else           v = *(const float4*)&g_hb[(size_t)r * ND + ((tid - 128) << 2)];

    float s = v.x + v.y + v.z + v.w;
    float q = v.x * v.x + v.y * v.y + v.z * v.z + v.w * v.w;
#pragma unroll
    for (int o = 16; o; o >>= 1) {
        s += __shfl_down_sync(0xffffffffu, s, o);
        q += __shfl_down_sync(0xffffffffu, q, o);
    }
    if ((tid & 31) == 0) { red[tid >> 5] = s; red[8 + (tid >> 5)] = q; }
    __syncthreads();
    if (tid == 0) {
        float S = 0.f, Q = 0.f;
#pragma unroll
        for (int i = 0; i < 8; ++i) { S += red[i]; Q += red[8 + i]; }
        float mu = S * (1.f / 1024.f);
        float var = Q * (1.f / 1024.f) - mu * mu;
        s_mu = mu;
        s_rs = rsqrtf(var + 1e-6f);
    }
    __syncthreads();
    float mu = s_mu, rs = s_rs;
    int col = tid << 2;
    float4 g4 = *(const float4*)&gamma[col];
    float4 b4 = *(const float4*)&beta[col];
    float4 xv = *(const float4*)&x[(size_t)r * NI + col];
    float4 o;
    o.x = xv.x + (v.x - mu) * rs * g4.x + b4.x;
    o.y = xv.y + (v.y - mu) * rs * g4.y + b4.y;
    o.z = xv.z + (v.z - mu) * rs * g4.z + b4.z;
    o.w = xv.w + (v.w - mu) * rs * g4.w + b4.w;
    *(float4*)&out[(size_t)r * NI + col] = o;
}

// ---------- host launch ----------
extern "C" void kernel_launch(void* const* d_in, const int* in_sizes, int n_in,
                              void* d_out, int out_size)
{
    const float* x     = (const float*)d_in[0];
    const float* W1    = (const float*)d_in[1];
    const float* U1    = (const float*)d_in[2];
    const float* b1    = (const float*)d_in[3];
    const float* Wf    = (const float*)d_in[4];
    const float* Uf    = (const float*)d_in[5];
    const float* bf    = (const float*)d_in[6];
    const float* Wb    = (const float*)d_in[7];
    const float* Ub    = (const float*)d_in[8];
    const float* bb    = (const float*)d_in[9];
    const float* gamma = (const float*)d_in[10];
    const float* beta  = (const float*)d_in[11];
    float* out = (float*)d_out;

    void *p_xw1, *p_xwf, *p_xwb, *p_h1;
    cudaGetSymbolAddress(&p_xw1, g_xw1);
    cudaGetSymbolAddress(&p_xwf, g_xwf);
    cudaGetSymbolAddress(&p_xwb, g_xwb);
    cudaGetSymbolAddress(&p_h1,  g_h1);

    cudaFuncSetAttribute(lstm1_kernel,  cudaFuncAttributeMaxDynamicSharedMemorySize, SMEM_L1);
    cudaFuncSetAttribute(lstmfb_kernel, cudaFuncAttributeMaxDynamicSharedMemorySize, SMEM_FB);

    const int M = NB * NT;
    dim3 gg(NG / GBN, M / GBM);

    reset_bars_kernel<<<1, 1>>>();
    sgemm_bias_kernel<<<gg, 256>>>(x, W1, b1, (float*)p_xw1, M, NG, NI);
    lstm1_kernel<<<NCTA, 256, SMEM_L1>>>(U1);
    sgemm_bias_kernel<<<gg, 256>>>((const float*)p_h1, Wf, bf, (float*)p_xwf, M, NG, ND);
    sgemm_bias_kernel<<<gg, 256>>>((const float*)p_h1, Wb, bb, (float*)p_xwb, M, NG, ND);
    lstmfb_kernel<<<NCTA, 256, SMEM_FB>>>(Uf, Ub);
    ln_kernel<<<M, 256>>>(x, gamma, beta, out);
}

// round 5
// speedup vs baseline: 1.5544x; 1.3060x over previous
#include <cuda_runtime.h>

#define NB 64
#define NT 512
#define ND 512
#define NI 1024
#define NG 2048
#define NCTA 128

typedef unsigned long long ull;

// scratch (static device memory; no cudaMalloc allowed)
__device__ __align__(16) float g_xw1[(size_t)NB * NT * NG];
__device__ __align__(16) float g_xwf[(size_t)NB * NT * NG];
__device__ __align__(16) float g_xwb[(size_t)NB * NT * NG];
__device__ __align__(16) float g_h1 [(size_t)NB * NT * ND];   // [b][t][u]
__device__ __align__(16) float g_hf [(size_t)NB * NT * ND];
__device__ __align__(16) float g_hb [(size_t)NB * NT * ND];
__device__ __align__(16) float g_h1t[(size_t)NT * ND * NB];   // [t][u][b]
__device__ __align__(16) float g_hft[(size_t)NT * ND * NB];
__device__ __align__(16) float g_hbt[(size_t)NT * ND * NB];
__device__ unsigned g_bar1;
__device__ unsigned g_bar2;

// ---------- packed f32x2 ----------
__device__ __forceinline__ ull pack2(float lo, float hi) {
    ull v; asm("mov.b64 %0, {%1, %2};" : "=l"(v) : "f"(lo), "f"(hi)); return v;
}
__device__ __forceinline__ float2 unpack2(ull v) {
    float lo, hi; asm("mov.b64 {%0, %1}, %2;" : "=f"(lo), "=f"(hi) : "l"(v));
    return make_float2(lo, hi);
}
__device__ __forceinline__ void ffma2(ull& c, ull a, ull b) {
    asm("fma.rn.f32x2 %0, %1, %2, %0;" : "+l"(c) : "l"(a), "l"(b));
}
__device__ __forceinline__ float sigm(float z) { return 1.f / (1.f + __expf(-z)); }

// ---------- grid-wide spin barrier ----------
__device__ __forceinline__ void grid_barrier(unsigned* bar, unsigned target) {
    __threadfence();
    __syncthreads();
    if (threadIdx.x == 0) {
        atomicAdd(bar, 1u);
        while (*((volatile unsigned*)bar) < target) { }
        __threadfence();
    }
    __syncthreads();
}

__global__ void reset_bars_kernel() { g_bar1 = 0u; g_bar2 = 0u; }

// ---------- SGEMM (unchanged: fma=74.6% of FFMA2 roofline) ----------
#define GBM 128
#define GBN 128
#define GBK 16

__global__ __launch_bounds__(256, 1) void sgemm_bias_kernel(
    const float* __restrict__ A, const float* __restrict__ W,
    const float* __restrict__ bias, float* __restrict__ C,
    int M, int N, int K)
{
    __shared__ __align__(16) float As[GBK][GBM + 4];
    __shared__ __align__(16) float Bs[GBK][GBN + 4];

    const int tid = threadIdx.x;
    const int n0 = blockIdx.x * GBN;
    const int m0 = blockIdx.y * GBM;
    const int tx = tid & 15;
    const int ty = tid >> 4;

    ull acc[8][4];
#pragma unroll
    for (int i = 0; i < 8; ++i)
#pragma unroll
        for (int j = 0; j < 4; ++j) acc[i][j] = 0ull;

    for (int k0 = 0; k0 < K; k0 += GBK) {
#pragma unroll
        for (int i = 0; i < 2; ++i) {
            int idx = i * 256 + tid;
            int row = idx >> 2;
            int c4 = (idx & 3) << 2;
            float4 av = *(const float4*)&A[(size_t)(m0 + row) * K + k0 + c4];
            As[c4 + 0][row] = av.x; As[c4 + 1][row] = av.y;
            As[c4 + 2][row] = av.z; As[c4 + 3][row] = av.w;
        }
#pragma unroll
        for (int i = 0; i < 2; ++i) {
            int idx = i * 256 + tid;
            int r = idx >> 5;
            int c4 = (idx & 31) << 2;
            *(float4*)&Bs[r][c4] = *(const float4*)&W[(size_t)(k0 + r) * N + n0 + c4];
        }
        __syncthreads();

#pragma unroll
        for (int k = 0; k < GBK; ++k) {
            float4 a0 = *(float4*)&As[k][ty * 4];
            float4 a1 = *(float4*)&As[k][64 + ty * 4];
            float4 b0 = *(float4*)&Bs[k][tx * 4];
            float4 b1 = *(float4*)&Bs[k][64 + tx * 4];
            float ra[8] = {a0.x, a0.y, a0.z, a0.w, a1.x, a1.y, a1.z, a1.w};
            ull bp[4] = {pack2(b0.x, b0.y), pack2(b0.z, b0.w),
                         pack2(b1.x, b1.y), pack2(b1.z, b1.w)};
#pragma unroll
            for (int i = 0; i < 8; ++i) {
                ull a2 = pack2(ra[i], ra[i]);
#pragma unroll
                for (int j = 0; j < 4; ++j) ffma2(acc[i][j], a2, bp[j]);
            }
        }
        __syncthreads();
    }

    float4 bv0 = *(const float4*)&bias[n0 + tx * 4];
    float4 bv1 = *(const float4*)&bias[n0 + 64 + tx * 4];
#pragma unroll
    for (int i = 0; i < 8; ++i) {
        int row = (i < 4) ? (ty * 4 + i) : (64 + ty * 4 + (i - 4));
        float* cp = &C[(size_t)(m0 + row) * N + n0];
        float2 a0 = unpack2(acc[i][0]), a1 = unpack2(acc[i][1]);
        float2 a2 = unpack2(acc[i][2]), a3 = unpack2(acc[i][3]);
        float4 o0 = make_float4(a0.x + bv0.x, a0.y + bv0.y, a1.x + bv0.z, a1.y + bv0.w);
        float4 o1 = make_float4(a2.x + bv1.x, a2.y + bv1.y, a3.x + bv1.z, a3.y + bv1.w);
        *(float4*)&cp[tx * 4] = o0;
        *(float4*)&cp[64 + tx * 4] = o1;
    }
}

// ================= LSTM recurrence v3 =================
// Compute map: warp = ke (k-eighth, k = i*8+ke), lane = b2 (batch-pair).
// Thread accumulates all 16 gate-cols (4 units x (i,f)(g,o) f32x2 pairs) x 2 batches.
// Gate map: gb = tid&63 (batch), gu = tid>>6 (unit). Us[k*16 + u*4 + {i,f,g,o}].

__device__ __forceinline__ void load_U_shared(float* Us, const float* __restrict__ U,
                                              int u0, int tid) {
    for (int idx = tid; idx < 8192; idx += 256) {
        int k = idx >> 4, r = idx & 15;
        int u = r >> 2, g = r & 3;
        Us[idx] = U[(size_t)k * NG + (size_t)g * ND + u0 + u];
    }
}

__device__ __forceinline__ void stage_ld(float4* r, const float* __restrict__ ht,
                                         int t, int c, int tid) {
    const float4* src = (const float4*)(ht + ((size_t)t * ND + c * 64) * NB);
#pragma unroll
    for (int j = 0; j < 4; ++j) r[j] = src[j * 256 + tid];
}

__device__ __forceinline__ void stage_st(float* dst, const float4* r, int tid) {
#pragma unroll
    for (int j = 0; j < 4; ++j) {
        int flat = j * 256 + tid;             // float4 index within 64k x 64b chunk
        int kl = flat >> 4, b4 = (flat & 15) << 2;
        *(float4*)&dst[kl * 64 + b4] = r[j];
    }
}

__device__ __forceinline__ void compute_chunk(const float* hs, const float* Us,
                                              int c, int ke, int b2, ull* acc) {
#pragma unroll
    for (int ii = 0; ii < 8; ++ii) {
        int kl = ii * 8 + ke;
        float2 hv = *(const float2*)&hs[kl * 64 + (b2 << 1)];
        ull a0 = pack2(hv.x, hv.x);
        ull a1 = pack2(hv.y, hv.y);
        const ulonglong2* uvp = (const ulonglong2*)&Us[(((c << 6) + kl) << 4)];
#pragma unroll
        for (int u = 0; u < 4; ++u) {
            ulonglong2 uv = uvp[u];
            ffma2(acc[(0 * 4 + u) * 2 + 0], a0, uv.x);
            ffma2(acc[(0 * 4 + u) * 2 + 1], a0, uv.y);
            ffma2(acc[(1 * 4 + u) * 2 + 0], a1, uv.x);
            ffma2(acc[(1 * 4 + u) * 2 + 1], a1, uv.y);
        }
    }
}

__device__ __forceinline__ void accum(const float* __restrict__ ht, int t,
                                      const float* Us, float* h0, float* h1b,
                                      int tid, int ke, int b2, ull* acc) {
    float4 r[4];
    stage_ld(r, ht, t, 0, tid);
    stage_st(h0, r, tid);
    __syncthreads();
#pragma unroll 1
    for (int c = 0; c < 8; ++c) {
        const float* cur = (c & 1) ? h1b : h0;
        float* nxt = (c & 1) ? h0 : h1b;
        if (c < 7) stage_ld(r, ht, t, c + 1, tid);
        compute_chunk(cur, Us, c, ke, b2, acc);
        if (c < 7) stage_st(nxt, r, tid);
        __syncthreads();
    }
}

__device__ __forceinline__ void stage_zs(float* zs, const float* __restrict__ xw,
                                         int t, int u0, int tid) {
    int bb = tid >> 2, g = tid & 3;
    float4 xv = *(const float4*)&xw[((size_t)bb * NT + t) * NG + (size_t)g * ND + u0];
    *(float4*)&zs[bb * 20 + (g << 2)] = xv;
}

// scr: 64 rows x 132 floats (row = batch; cols = ke*16 + u*4 + gate)
__device__ __forceinline__ void gate(float* __restrict__ h_btu, float* __restrict__ h_tub,
                                     int t, int u0, const ull* acc, float& cst,
                                     const float* zs, float* scr, float* shs,
                                     int tid, int ke, int b2, int gb, int gu) {
    ull* scr_u = (ull*)scr;
#pragma unroll
    for (int bb = 0; bb < 2; ++bb)
#pragma unroll
        for (int u = 0; u < 4; ++u)
#pragma unroll
            for (int p = 0; p < 2; ++p)
                scr_u[(size_t)(((b2 << 1) | bb) * 66 + (ke << 3) + (u << 1) + p)] =
                    acc[(bb * 4 + u) * 2 + p];
    __syncthreads();

    float4 z = make_float4(0.f, 0.f, 0.f, 0.f);
#pragma unroll
    for (int k = 0; k < 8; ++k) {
        float4 part = *(const float4*)&scr[gb * 132 + (k << 4) + (gu << 2)];
        z.x += part.x; z.y += part.y; z.z += part.z; z.w += part.w;
    }
    float zi = z.x + zs[gb * 20 + gu];
    float zf = z.y + zs[gb * 20 + 4 + gu];
    float zg = z.z + zs[gb * 20 + 8 + gu];
    float zo = z.w + zs[gb * 20 + 12 + gu];
    float ig = sigm(zi), fg = sigm(zf);
    float gv = fmaxf(zg, 0.f), og = sigm(zo);
    cst = fmaf(fg, cst, ig * gv);
    float h = og * fmaxf(cst, 0.f);

    h_tub[((size_t)t * ND + u0 + gu) * NB + gb] = h;   // coalesced transposed copy
    shs[(gb << 2) + gu] = h;
    __syncthreads();
    if (tid < 64) {
        float4 h4 = *(const float4*)&shs[tid << 2];
        *(float4*)&h_btu[((size_t)tid * NT + t) * ND + u0] = h4;
    }
}

// ---------- LSTM1 persistent ----------
// smem floats: Us 8192 | hA 4096 | hB 4096 | zs 1280 | scr 8448 | shs 256 = 26368
#define SMEM_L1 (26368 * 4)

__global__ __launch_bounds__(256) void lstm1_kernel(const float* __restrict__ U)
{
    extern __shared__ float sm[];
    float* Us  = sm;
    float* hA  = sm + 8192;
    float* hB  = sm + 12288;
    float* zs  = sm + 16384;
    float* scr = sm + 17664;
    float* shs = sm + 26112;

    const int tid = threadIdx.x;
    const int ke = tid >> 5, b2 = tid & 31;
    const int gb = tid & 63, gu = tid >> 6;
    const int u0 = blockIdx.x << 2;

    load_U_shared(Us, U, u0, tid);
    __syncthreads();

    float cst = 0.f;
    for (int t = 0; t < NT; ++t) {
        stage_zs(zs, g_xw1, t, u0, tid);
        ull acc[16];
#pragma unroll
        for (int i = 0; i < 16; ++i) acc[i] = 0ull;
        if (t > 0) {
            grid_barrier(&g_bar1, (unsigned)t * NCTA);
            accum(g_h1t, t - 1, Us, hA, hB, tid, ke, b2, acc);
        } else {
            __syncthreads();
        }
        gate(g_h1, g_h1t, t, u0, acc, cst, zs, scr, shs, tid, ke, b2, gb, gu);
    }
}

// ---------- fused fwd+bwd LSTM persistent ----------
// smem floats: Ufs 8192 | Ubs 8192 | hA 4096 | hB 4096 | zsf 1280 | zsb 1280 | scr 8448 | shs 256 = 35840
#define SMEM_FB (35840 * 4)

__global__ __launch_bounds__(256) void lstmfb_kernel(
    const float* __restrict__ Uf, const float* __restrict__ Ub)
{
    extern __shared__ float sm[];
    float* Ufs = sm;
    float* Ubs = sm + 8192;
    float* hA  = sm + 16384;
    float* hB  = sm + 20480;
    float* zsf = sm + 24576;
    float* zsb = sm + 25856;
    float* scr = sm + 27136;
    float* shs = sm + 35584;

    const int tid = threadIdx.x;
    const int ke = tid >> 5, b2 = tid & 31;
    const int gb = tid & 63, gu = tid >> 6;
    const int u0 = blockIdx.x << 2;

    load_U_shared(Ufs, Uf, u0, tid);
    load_U_shared(Ubs, Ub, u0, tid);
    __syncthreads();

    float cf = 0.f, cb = 0.f;
    for (int s = 0; s < NT; ++s) {
        int tf = s, tb = NT - 1 - s;
        stage_zs(zsf, g_xwf, tf, u0, tid);
        stage_zs(zsb, g_xwb, tb, u0, tid);
        ull af[16], ab[16];
#pragma unroll
        for (int i = 0; i < 16; ++i) { af[i] = 0ull; ab[i] = 0ull; }
        if (s > 0) {
            grid_barrier(&g_bar2, (unsigned)s * NCTA);
            accum(g_hft, tf - 1, Ufs, hA, hB, tid, ke, b2, af);
            gate(g_hf, g_hft, tf, u0, af, cf, zsf, scr, shs, tid, ke, b2, gb, gu);
            accum(g_hbt, tb + 1, Ubs, hA, hB, tid, ke, b2, ab);
            gate(g_hb, g_hbt, tb, u0, ab, cb, zsb, scr, shs, tid, ke, b2, gb, gu);
        } else {
            __syncthreads();
            gate(g_hf, g_hft, tf, u0, af, cf, zsf, scr, shs, tid, ke, b2, gb, gu);
            gate(g_hb, g_hbt, tb, u0, ab, cb, zsb, scr, shs, tid, ke, b2, gb, gu);
        }
    }
}

// ---------- LayerNorm(concat(hf,hb)) * gamma + beta + x ----------
__global__ __launch_bounds__(256) void ln_kernel(
    const float* __restrict__ x, const float* __restrict__ gamma,
    const float* __restrict__ beta, float* __restrict__ out)
{
    __shared__ float red[16];
    __shared__ float s_mu, s_rs;
    const int r = blockIdx.x;
    const int tid = threadIdx.x;

    float4 v;
    if (tid < 128) v = *(const float4*)&g_hf[(size_t)r * ND + (tid << 2)];
    else           v = *(const float4*)&g_hb[(size_t)r * ND + ((tid - 128) << 2)];

    float s = v.x + v.y + v.z + v.w;
    float q = v.x * v.x + v.y * v.y + v.z * v.z + v.w * v.w;
#pragma unroll
    for (int o = 16; o; o >>= 1) {
        s += __shfl_down_sync(0xffffffffu, s, o);
        q += __shfl_down_sync(0xffffffffu, q, o);
    }
    if ((tid & 31) == 0) { red[tid >> 5] = s; red[8 + (tid >> 5)] = q; }
    __syncthreads();
    if (tid == 0) {
        float S = 0.f, Q = 0.f;
#pragma unroll
        for (int i = 0; i < 8; ++i) { S += red[i]; Q += red[8 + i]; }
        float mu = S * (1.f / 1024.f);
        float var = Q * (1.f / 1024.f) - mu * mu;
        s_mu = mu;
        s_rs = rsqrtf(var + 1e-6f);
    }
    __syncthreads();
    float mu = s_mu, rs = s_rs;
    int col = tid << 2;
    float4 g4 = *(const float4*)&gamma[col];
    float4 b4 = *(const float4*)&beta[col];
    float4 xv = *(const float4*)&x[(size_t)r * NI + col];
    float4 o;
    o.x = xv.x + (v.x - mu) * rs * g4.x + b4.x;
    o.y = xv.y + (v.y - mu) * rs * g4.y + b4.y;
    o.z = xv.z + (v.z - mu) * rs * g4.z + b4.z;
    o.w = xv.w + (v.w - mu) * rs * g4.w + b4.w;
    *(float4*)&out[(size_t)r * NI + col] = o;
}

// ---------- host launch ----------
extern "C" void kernel_launch(void* const* d_in, const int* in_sizes, int n_in,
                              void* d_out, int out_size)
{
    const float* x     = (const float*)d_in[0];
    const float* W1    = (const float*)d_in[1];
    const float* U1    = (const float*)d_in[2];
    const float* b1    = (const float*)d_in[3];
    const float* Wf    = (const float*)d_in[4];
    const float* Uf    = (const float*)d_in[5];
    const float* bf    = (const float*)d_in[6];
    const float* Wb    = (const float*)d_in[7];
    const float* Ub    = (const float*)d_in[8];
    const float* bb    = (const float*)d_in[9];
    const float* gamma = (const float*)d_in[10];
    const float* beta  = (const float*)d_in[11];
    float* out = (float*)d_out;

    void *p_xw1, *p_xwf, *p_xwb, *p_h1;
    cudaGetSymbolAddress(&p_xw1, g_xw1);
    cudaGetSymbolAddress(&p_xwf, g_xwf);
    cudaGetSymbolAddress(&p_xwb, g_xwb);
    cudaGetSymbolAddress(&p_h1,  g_h1);

    cudaFuncSetAttribute(lstm1_kernel,  cudaFuncAttributeMaxDynamicSharedMemorySize, SMEM_L1);
    cudaFuncSetAttribute(lstmfb_kernel, cudaFuncAttributeMaxDynamicSharedMemorySize, SMEM_FB);

    const int M = NB * NT;
    dim3 gg(NG / GBN, M / GBM);

    reset_bars_kernel<<<1, 1>>>();
    sgemm_bias_kernel<<<gg, 256>>>(x, W1, b1, (float*)p_xw1, M, NG, NI);
    lstm1_kernel<<<NCTA, 256, SMEM_L1>>>(U1);
    sgemm_bias_kernel<<<gg, 256>>>((const float*)p_h1, Wf, bf, (float*)p_xwf, M, NG, ND);
    sgemm_bias_kernel<<<gg, 256>>>((const float*)p_h1, Wb, bb, (float*)p_xwb, M, NG, ND);
    lstmfb_kernel<<<NCTA, 256, SMEM_FB>>>(Uf, Ub);
    ln_kernel<<<M, 256>>>(x, gamma, beta, out);
}

// round 7
// speedup vs baseline: 1.5636x; 1.0060x over previous
#include <cuda_runtime.h>
#include <cstdint>

#define NB 64
#define NT 512
#define ND 512
#define NI 1024
#define NG 2048
#define NCTA 128

typedef unsigned long long ull;

// ---------------- static device scratch ----------------
__device__ __align__(16) float g_xw1[(size_t)NB * NT * NG];
__device__ __align__(16) float g_xwf[(size_t)NB * NT * NG];
__device__ __align__(16) float g_xwb[(size_t)NB * NT * NG];
__device__ __align__(16) float g_h1 [(size_t)NB * NT * ND];   // [b][t][u]
__device__ __align__(16) float g_hf [(size_t)NB * NT * ND];
__device__ __align__(16) float g_hb [(size_t)NB * NT * ND];
__device__ __align__(16) float g_h1t[(size_t)NT * ND * NB];   // [t][u][b]
__device__ __align__(16) float g_hft[(size_t)NT * ND * NB];
__device__ __align__(16) float g_hbt[(size_t)NT * ND * NB];
__device__ __align__(16) float g_Wt1[(size_t)NG * NI];        // W1^T
__device__ __align__(16) float g_Wtf[(size_t)NG * ND];        // Wf^T
__device__ __align__(16) float g_Wtb[(size_t)NG * ND];        // Wb^T
__device__ unsigned g_bar1;
__device__ unsigned g_bar2;

// ---------------- packed f32x2 helpers ----------------
__device__ __forceinline__ ull pack2(float lo, float hi) {
    ull v; asm("mov.b64 %0, {%1, %2};" : "=l"(v) : "f"(lo), "f"(hi)); return v;
}
__device__ __forceinline__ float2 unpack2(ull v) {
    float lo, hi; asm("mov.b64 {%0, %1}, %2;" : "=f"(lo), "=f"(hi) : "l"(v));
    return make_float2(lo, hi);
}
__device__ __forceinline__ void ffma2(ull& c, ull a, ull b) {
    asm("fma.rn.f32x2 %0, %1, %2, %0;" : "+l"(c) : "l"(a), "l"(b));
}
__device__ __forceinline__ float sigm(float z) { return 1.f / (1.f + __expf(-z)); }

// ---------------- grid-wide spin barrier ----------------
__device__ __forceinline__ void grid_barrier(unsigned* bar, unsigned target) {
    __threadfence();
    __syncthreads();
    if (threadIdx.x == 0) {
        atomicAdd(bar, 1u);
        while (*((volatile unsigned*)bar) < target) { }
        __threadfence();
    }
    __syncthreads();
}

__global__ void reset_bars_kernel() { g_bar1 = 0u; g_bar2 = 0u; }

// ================= tf32 mma.sync GEMM (3xTF32 split, fp32-accurate) =================
// C[M, N=2048] = A[M,K] @ Bt[N,K]^T + bias. CTA tile 128x128, K-chunk 16.
// 8 warps: warp_m = wid&3 (32 rows), warp_n = wid>>2 (64 cols); 2x8 m16n8k8 tiles.

#define GSTRIDE 20              // smem row stride (floats): conflict-free for frags+stage
#define GARR (128 * GSTRIDE)    // 2560 floats per tile array
#define SMEM_GEMM (8 * GARR * 4)  // 4 arrays x 2 buffers = 81920 B

__device__ __forceinline__ float tf32_rna(float x) {
    float r; asm("cvt.rna.tf32.f32 %0, %1;" : "=f"(r) : "f"(x)); return r;
}
__device__ __forceinline__ void mma_tf32(float* d, const uint32_t* a, const uint32_t* b) {
    asm volatile(
        "mma.sync.aligned.m16n8k8.row.col.f32.tf32.tf32.f32 "
        "{%0,%1,%2,%3}, {%4,%5,%6,%7}, {%8,%9}, {%0,%1,%2,%3};"
        : "+f"(d[0]), "+f"(d[1]), "+f"(d[2]), "+f"(d[3])
        : "r"(a[0]), "r"(a[1]), "r"(a[2]), "r"(a[3]), "r"(b[0]), "r"(b[1]));
}

__device__ __forceinline__ void g_stage_ld(float4* r, const float* __restrict__ src,
                                           int K, int k0, int tid) {
#pragma unroll
    for (int j = 0; j < 2; ++j) {
        int idx = j * 256 + tid;
        int row = idx >> 2, k4 = (idx & 3) << 2;
        r[j] = *(const float4*)&src[(size_t)row * K + k0 + k4];
    }
}
__device__ __forceinline__ void g_stage_st(float* hi, float* lo, const float4* r, int tid) {
#pragma unroll
    for (int j = 0; j < 2; ++j) {
        int idx = j * 256 + tid;
        int row = idx >> 2, k4 = (idx & 3) << 2;
        float4 v = r[j], h, l;
        h.x = tf32_rna(v.x); h.y = tf32_rna(v.y); h.z = tf32_rna(v.z); h.w = tf32_rna(v.w);
        l.x = tf32_rna(v.x - h.x); l.y = tf32_rna(v.y - h.y);
        l.z = tf32_rna(v.z - h.z); l.w = tf32_rna(v.w - h.w);
        *(float4*)&hi[row * GSTRIDE + k4] = h;
        *(float4*)&lo[row * GSTRIDE + k4] = l;
    }
}

__global__ __launch_bounds__(256, 1) void gemm_mma_kernel(
    const float* __restrict__ A, const float* __restrict__ Bt,
    const float* __restrict__ bias, float* __restrict__ C, int K)
{
    extern __shared__ float sg[];
    const int tid = threadIdx.x;
    const int wid = tid >> 5, lane = tid & 31;
    const int lr = lane >> 2, lc = lane & 3;
    const int warp_m = wid & 3, warp_n = wid >> 2;
    const int n0 = blockIdx.x * 128, m0 = blockIdx.y * 128;

    const float* Abase = A + (size_t)m0 * K;
    const float* Bbase = Bt + (size_t)n0 * K;

    float acc[2][8][4];
#pragma unroll
    for (int mt = 0; mt < 2; ++mt)
#pragma unroll
        for (int nt = 0; nt < 8; ++nt)
#pragma unroll
            for (int q = 0; q < 4; ++q) acc[mt][nt][q] = 0.f;

    const int nc = K >> 4;
    float4 rA[2], rB[2];

    g_stage_ld(rA, Abase, K, 0, tid);
    g_stage_ld(rB, Bbase, K, 0, tid);
    g_stage_st(sg + 0 * GARR, sg + 1 * GARR, rA, tid);
    g_stage_st(sg + 2 * GARR, sg + 3 * GARR, rB, tid);
    __syncthreads();

#pragma unroll 1
    for (int c = 0; c < nc; ++c) {
        const int buf = c & 1;
        if (c + 1 < nc) {
            g_stage_ld(rA, Abase, K, (c + 1) << 4, tid);
            g_stage_ld(rB, Bbase, K, (c + 1) << 4, tid);
        }
        const uint32_t* sAh = (const uint32_t*)(sg + buf * 4 * GARR + 0 * GARR);
        const uint32_t* sAl = (const uint32_t*)(sg + buf * 4 * GARR + 1 * GARR);
        const uint32_t* sBh = (const uint32_t*)(sg + buf * 4 * GARR + 2 * GARR);
        const uint32_t* sBl = (const uint32_t*)(sg + buf * 4 * GARR + 3 * GARR);

#pragma unroll
        for (int ks = 0; ks < 16; ks += 8) {
            uint32_t ah[2][4], al[2][4];
#pragma unroll
            for (int mt = 0; mt < 2; ++mt) {
                int row = warp_m * 32 + mt * 16 + lr;
                ah[mt][0] = sAh[row * GSTRIDE + ks + lc];
                ah[mt][1] = sAh[(row + 8) * GSTRIDE + ks + lc];
                ah[mt][2] = sAh[row * GSTRIDE + ks + lc + 4];
                ah[mt][3] = sAh[(row + 8) * GSTRIDE + ks + lc + 4];
                al[mt][0] = sAl[row * GSTRIDE + ks + lc];
                al[mt][1] = sAl[(row + 8) * GSTRIDE + ks + lc];
                al[mt][2] = sAl[row * GSTRIDE + ks + lc + 4];
                al[mt][3] = sAl[(row + 8) * GSTRIDE + ks + lc + 4];
            }
            uint32_t bh[8][2], bl[8][2];
#pragma unroll
            for (int nt = 0; nt < 8; ++nt) {
                int n = warp_n * 64 + nt * 8 + lr;
                bh[nt][0] = sBh[n * GSTRIDE + ks + lc];
                bh[nt][1] = sBh[n * GSTRIDE + ks + lc + 4];
                bl[nt][0] = sBl[n * GSTRIDE + ks + lc];
                bl[nt][1] = sBl[n * GSTRIDE + ks + lc + 4];
            }
#pragma unroll
            for (int mt = 0; mt < 2; ++mt)
#pragma unroll
                for (int nt = 0; nt < 8; ++nt) {
                    mma_tf32(acc[mt][nt], ah[mt], bh[nt]);
                    mma_tf32(acc[mt][nt], al[mt], bh[nt]);
                    mma_tf32(acc[mt][nt], ah[mt], bl[nt]);
                }
        }
        if (c + 1 < nc) {
            const int nb = (c + 1) & 1;
            g_stage_st(sg + nb * 4 * GARR + 0 * GARR, sg + nb * 4 * GARR + 1 * GARR, rA, tid);
            g_stage_st(sg + nb * 4 * GARR + 2 * GARR, sg + nb * 4 * GARR + 3 * GARR, rB, tid);
        }
        __syncthreads();
    }

    // epilogue: acc + bias -> C
#pragma unroll
    for (int mt = 0; mt < 2; ++mt) {
        int row = m0 + warp_m * 32 + mt * 16 + lr;
#pragma unroll
        for (int nt = 0; nt < 8; ++nt) {
            int col = n0 + warp_n * 64 + nt * 8 + 2 * lc;
            float2 bv = *(const float2*)&bias[col];
            float2 o0 = make_float2(acc[mt][nt][0] + bv.x, acc[mt][nt][1] + bv.y);
            float2 o1 = make_float2(acc[mt][nt][2] + bv.x, acc[mt][nt][3] + bv.y);
            *(float2*)&C[(size_t)row * NG + col] = o0;
            *(float2*)&C[(size_t)(row + 8) * NG + col] = o1;
        }
    }
}

// ---------------- weight transpose: Wt[n][k] = W[k][n] ----------------
__global__ __launch_bounds__(256) void transpose_kernel(
    const float* __restrict__ W, float* __restrict__ Wt, int K, int N)
{
    __shared__ float t[32][33];
    const int tx = threadIdx.x & 31, ty = threadIdx.x >> 5;
    const int n0 = blockIdx.x << 5, k0 = blockIdx.y << 5;
#pragma unroll
    for (int i = 0; i < 32; i += 8)
        t[ty + i][tx] = W[(size_t)(k0 + ty + i) * N + n0 + tx];
    __syncthreads();
#pragma unroll
    for (int i = 0; i < 32; i += 8)
        Wt[(size_t)(n0 + ty + i) * K + k0 + tx] = t[tx][ty + i];
}

// ================= LSTM recurrence (unchanged from R4 passing version) =================
__device__ __forceinline__ void load_U_shared(float* Us, const float* __restrict__ U,
                                              int u0, int tid) {
    for (int idx = tid; idx < 8192; idx += 256) {
        int k = idx >> 4, r = idx & 15;
        int u = r >> 2, g = r & 3;
        Us[idx] = U[(size_t)k * NG + (size_t)g * ND + u0 + u];
    }
}

__device__ __forceinline__ void stage_ld(float4* r, const float* __restrict__ ht,
                                         int t, int c, int tid) {
    const float4* src = (const float4*)(ht + ((size_t)t * ND + c * 64) * NB);
#pragma unroll
    for (int j = 0; j < 4; ++j) r[j] = src[j * 256 + tid];
}

__device__ __forceinline__ void stage_st(float* dst, const float4* r, int tid) {
#pragma unroll
    for (int j = 0; j < 4; ++j) {
        int flat = j * 256 + tid;
        int kl = flat >> 4, b4 = (flat & 15) << 2;
        *(float4*)&dst[kl * 64 + b4] = r[j];
    }
}

__device__ __forceinline__ void compute_chunk(const float* hs, const float* Us,
                                              int c, int ke, int b2, ull* acc) {
#pragma unroll
    for (int ii = 0; ii < 8; ++ii) {
        int kl = ii * 8 + ke;
        float2 hv = *(const float2*)&hs[kl * 64 + (b2 << 1)];
        ull a0 = pack2(hv.x, hv.x);
        ull a1 = pack2(hv.y, hv.y);
        const ulonglong2* uvp = (const ulonglong2*)&Us[(((c << 6) + kl) << 4)];
#pragma unroll
        for (int u = 0; u < 4; ++u) {
            ulonglong2 uv = uvp[u];
            ffma2(acc[(0 * 4 + u) * 2 + 0], a0, uv.x);
            ffma2(acc[(0 * 4 + u) * 2 + 1], a0, uv.y);
            ffma2(acc[(1 * 4 + u) * 2 + 0], a1, uv.x);
            ffma2(acc[(1 * 4 + u) * 2 + 1], a1, uv.y);
        }
    }
}

__device__ __forceinline__ void accum(const float* __restrict__ ht, int t,
                                      const float* Us, float* h0, float* h1b,
                                      int tid, int ke, int b2, ull* acc) {
    float4 r[4];
    stage_ld(r, ht, t, 0, tid);
    stage_st(h0, r, tid);
    __syncthreads();
#pragma unroll 1
    for (int c = 0; c < 8; ++c) {
        const float* cur = (c & 1) ? h1b : h0;
        float* nxt = (c & 1) ? h0 : h1b;
        if (c < 7) stage_ld(r, ht, t, c + 1, tid);
        compute_chunk(cur, Us, c, ke, b2, acc);
        if (c < 7) stage_st(nxt, r, tid);
        __syncthreads();
    }
}

__device__ __forceinline__ void stage_zs(float* zs, const float* __restrict__ xw,
                                         int t, int u0, int tid) {
    int bb = tid >> 2, g = tid & 3;
    float4 xv = *(const float4*)&xw[((size_t)bb * NT + t) * NG + (size_t)g * ND + u0];
    *(float4*)&zs[bb * 20 + (g << 2)] = xv;
}

__device__ __forceinline__ void gate(float* __restrict__ h_btu, float* __restrict__ h_tub,
                                     int t, int u0, const ull* acc, float& cst,
                                     const float* zs, float* scr, float* shs,
                                     int tid, int ke, int b2, int gb, int gu) {
    ull* scr_u = (ull*)scr;
#pragma unroll
    for (int bb = 0; bb < 2; ++bb)
#pragma unroll
        for (int u = 0; u < 4; ++u)
#pragma unroll
            for (int p = 0; p < 2; ++p)
                scr_u[(size_t)(((b2 << 1) | bb) * 66 + (ke << 3) + (u << 1) + p)] =
                    acc[(bb * 4 + u) * 2 + p];
    __syncthreads();

    float4 z = make_float4(0.f, 0.f, 0.f, 0.f);
#pragma unroll
    for (int k = 0; k < 8; ++k) {
        float4 part = *(const float4*)&scr[gb * 132 + (k << 4) + (gu << 2)];
        z.x += part.x; z.y += part.y; z.z += part.z; z.w += part.w;
    }
    float zi = z.x + zs[gb * 20 + gu];
    float zf = z.y + zs[gb * 20 + 4 + gu];
    float zg = z.z + zs[gb * 20 + 8 + gu];
    float zo = z.w + zs[gb * 20 + 12 + gu];
    float ig = sigm(zi), fg = sigm(zf);
    float gv = fmaxf(zg, 0.f), og = sigm(zo);
    cst = fmaf(fg, cst, ig * gv);
    float h = og * fmaxf(cst, 0.f);

    h_tub[((size_t)t * ND + u0 + gu) * NB + gb] = h;
    shs[(gb << 2) + gu] = h;
    __syncthreads();
    if (tid < 64) {
        float4 h4 = *(const float4*)&shs[tid << 2];
        *(float4*)&h_btu[((size_t)tid * NT + t) * ND + u0] = h4;
    }
}

#define SMEM_L1 (26368 * 4)

__global__ __launch_bounds__(256) void lstm1_kernel(const float* __restrict__ U)
{
    extern __shared__ float sm[];
    float* Us  = sm;
    float* hA  = sm + 8192;
    float* hB  = sm + 12288;
    float* zs  = sm + 16384;
    float* scr = sm + 17664;
    float* shs = sm + 26112;

    const int tid = threadIdx.x;
    const int ke = tid >> 5, b2 = tid & 31;
    const int gb = tid & 63, gu = tid >> 6;
    const int u0 = blockIdx.x << 2;

    load_U_shared(Us, U, u0, tid);
    __syncthreads();

    float cst = 0.f;
    for (int t = 0; t < NT; ++t) {
        stage_zs(zs, g_xw1, t, u0, tid);
        ull acc16[16];
#pragma unroll
        for (int i = 0; i < 16; ++i) acc16[i] = 0ull;
        if (t > 0) {
            grid_barrier(&g_bar1, (unsigned)t * NCTA);
            accum(g_h1t, t - 1, Us, hA, hB, tid, ke, b2, acc16);
        } else {
            __syncthreads();
        }
        gate(g_h1, g_h1t, t, u0, acc16, cst, zs, scr, shs, tid, ke, b2, gb, gu);
    }
}

#define SMEM_FB (35840 * 4)

__global__ __launch_bounds__(256) void lstmfb_kernel(
    const float* __restrict__ Uf, const float* __restrict__ Ub)
{
    extern __shared__ float sm[];
    float* Ufs = sm;
    float* Ubs = sm + 8192;
    float* hA  = sm + 16384;
    float* hB  = sm + 20480;
    float* zsf = sm + 24576;
    float* zsb = sm + 25856;
    float* scr = sm + 27136;
    float* shs = sm + 35584;

    const int tid = threadIdx.x;
    const int ke = tid >> 5, b2 = tid & 31;
    const int gb = tid & 63, gu = tid >> 6;
    const int u0 = blockIdx.x << 2;

    load_U_shared(Ufs, Uf, u0, tid);
    load_U_shared(Ubs, Ub, u0, tid);
    __syncthreads();

    float cf = 0.f, cb = 0.f;
    for (int s = 0; s < NT; ++s) {
        int tf = s, tb = NT - 1 - s;
        stage_zs(zsf, g_xwf, tf, u0, tid);
        stage_zs(zsb, g_xwb, tb, u0, tid);
        ull af[16], ab[16];
#pragma unroll
        for (int i = 0; i < 16; ++i) { af[i] = 0ull; ab[i] = 0ull; }
        if (s > 0) {
            grid_barrier(&g_bar2, (unsigned)s * NCTA);
            accum(g_hft, tf - 1, Ufs, hA, hB, tid, ke, b2, af);
            gate(g_hf, g_hft, tf, u0, af, cf, zsf, scr, shs, tid, ke, b2, gb, gu);
            accum(g_hbt, tb + 1, Ubs, hA, hB, tid, ke, b2, ab);
            gate(g_hb, g_hbt, tb, u0, ab, cb, zsb, scr, shs, tid, ke, b2, gb, gu);
        } else {
            __syncthreads();
            gate(g_hf, g_hft, tf, u0, af, cf, zsf, scr, shs, tid, ke, b2, gb, gu);
            gate(g_hb, g_hbt, tb, u0, ab, cb, zsb, scr, shs, tid, ke, b2, gb, gu);
        }
    }
}

// ---------------- LayerNorm + residual ----------------
__global__ __launch_bounds__(256) void ln_kernel(
    const float* __restrict__ x, const float* __restrict__ gamma,
    const float* __restrict__ beta, float* __restrict__ out)
{
    __shared__ float red[16];
    __shared__ float s_mu, s_rs;
    const int r = blockIdx.x;
    const int tid = threadIdx.x;

    float4 v;
    if (tid < 128) v = *(const float4*)&g_hf[(size_t)r * ND + (tid << 2)];
    else           v = *(const float4*)&g_hb[(size_t)r * ND + ((tid - 128) << 2)];

    float s = v.x + v.y + v.z + v.w;
    float q = v.x * v.x + v.y * v.y + v.z * v.z + v.w * v.w;
#pragma unroll
    for (int o = 16; o; o >>= 1) {
        s += __shfl_down_sync(0xffffffffu, s, o);
        q += __shfl_down_sync(0xffffffffu, q, o);
    }
    if ((tid & 31) == 0) { red[tid >> 5] = s; red[8 + (tid >> 5)] = q; }
    __syncthreads();
    if (tid == 0) {
        float S = 0.f, Q = 0.f;
#pragma unroll
        for (int i = 0; i < 8; ++i) { S += red[i]; Q += red[8 + i]; }
        float mu = S * (1.f / 1024.f);
        float var = Q * (1.f / 1024.f) - mu * mu;
        s_mu = mu;
        s_rs = rsqrtf(var + 1e-6f);
    }
    __syncthreads();
    float mu = s_mu, rs = s_rs;
    int col = tid << 2;
    float4 g4 = *(const float4*)&gamma[col];
    float4 b4 = *(const float4*)&beta[col];
    float4 xv = *(const float4*)&x[(size_t)r * NI + col];
    float4 o;
    o.x = xv.x + (v.x - mu) * rs * g4.x + b4.x;
    o.y = xv.y + (v.y - mu) * rs * g4.y + b4.y;
    o.z = xv.z + (v.z - mu) * rs * g4.z + b4.z;
    o.w = xv.w + (v.w - mu) * rs * g4.w + b4.w;
    *(float4*)&out[(size_t)r * NI + col] = o;
}

// ---------------- host launch ----------------
extern "C" void kernel_launch(void* const* d_in, const int* in_sizes, int n_in,
                              void* d_out, int out_size)
{
    const float* x     = (const float*)d_in[0];
    const float* W1    = (const float*)d_in[1];
    const float* U1    = (const float*)d_in[2];
    const float* b1    = (const float*)d_in[3];
    const float* Wf    = (const float*)d_in[4];
    const float* Uf    = (const float*)d_in[5];
    const float* bf    = (const float*)d_in[6];
    const float* Wb    = (const float*)d_in[7];
    const float* Ub    = (const float*)d_in[8];
    const float* bb    = (const float*)d_in[9];
    const float* gamma = (const float*)d_in[10];
    const float* beta  = (const float*)d_in[11];
    float* out = (float*)d_out;

    void *p_xw1, *p_xwf, *p_xwb, *p_h1, *p_Wt1, *p_Wtf, *p_Wtb;
    cudaGetSymbolAddress(&p_xw1, g_xw1);
    cudaGetSymbolAddress(&p_xwf, g_xwf);
    cudaGetSymbolAddress(&p_xwb, g_xwb);
    cudaGetSymbolAddress(&p_h1,  g_h1);
    cudaGetSymbolAddress(&p_Wt1, g_Wt1);
    cudaGetSymbolAddress(&p_Wtf, g_Wtf);
    cudaGetSymbolAddress(&p_Wtb, g_Wtb);

    cudaFuncSetAttribute(lstm1_kernel,  cudaFuncAttributeMaxDynamicSharedMemorySize, SMEM_L1);
    cudaFuncSetAttribute(lstmfb_kernel, cudaFuncAttributeMaxDynamicSharedMemorySize, SMEM_FB);
    cudaFuncSetAttribute(gemm_mma_kernel, cudaFuncAttributeMaxDynamicSharedMemorySize, SMEM_GEMM);

    const int M = NB * NT;
    dim3 gg(NG / 128, M / 128);   // n-fast -> A-slice L2 reuse

    reset_bars_kernel<<<1, 1>>>();
    transpose_kernel<<<dim3(NG / 32, NI / 32), 256>>>(W1, (float*)p_Wt1, NI, NG);
    transpose_kernel<<<dim3(NG / 32, ND / 32), 256>>>(Wf, (float*)p_Wtf, ND, NG);
    transpose_kernel<<<dim3(NG / 32, ND / 32), 256>>>(Wb, (float*)p_Wtb, ND, NG);

    gemm_mma_kernel<<<gg, 256, SMEM_GEMM>>>(x, (const float*)p_Wt1, b1, (float*)p_xw1, NI);
    lstm1_kernel<<<NCTA, 256, SMEM_L1>>>(U1);
    gemm_mma_kernel<<<gg, 256, SMEM_GEMM>>>((const float*)p_h1, (const float*)p_Wtf, bf, (float*)p_xwf, ND);
    gemm_mma_kernel<<<gg, 256, SMEM_GEMM>>>((const float*)p_h1, (const float*)p_Wtb, bb, (float*)p_xwb, ND);
    lstmfb_kernel<<<NCTA, 256, SMEM_FB>>>(Uf, Ub);
    ln_kernel<<<M, 256>>>(x, gamma, beta, out);
}

// round 8
// speedup vs baseline: 1.6533x; 1.0573x over previous
#include <cuda_runtime.h>
#include <cuda_fp16.h>
#include <cstdint>

#define NB 64
#define NT 512
#define ND 512
#define NI 1024
#define NG 2048
#define NCTA 128

typedef unsigned long long ull;
typedef unsigned uint;

// ---------------- static device scratch ----------------
__device__ __align__(16) float g_xw1[(size_t)NB * NT * NG];
__device__ __align__(16) float g_xwf[(size_t)NB * NT * NG];
__device__ __align__(16) float g_xwb[(size_t)NB * NT * NG];
__device__ __align__(16) float g_h1 [(size_t)NB * NT * ND];   // [b][t][u]
__device__ __align__(16) float g_hf [(size_t)NB * NT * ND];
__device__ __align__(16) float g_hb [(size_t)NB * NT * ND];
__device__ __align__(16) float g_h1t[(size_t)NT * ND * NB];   // [t][u][b]
__device__ __align__(16) float g_hft[(size_t)NT * ND * NB];
__device__ __align__(16) float g_hbt[(size_t)NT * ND * NB];
__device__ __align__(16) float g_Wt1[(size_t)NG * NI];        // W1^T fp32
__device__ __align__(16) float g_Wtf[(size_t)NG * ND];
__device__ __align__(16) float g_Wtb[(size_t)NG * ND];
// fp16 split operand buffers (packed k-pairs as uint)
__device__ __align__(16) uint g_Ah [(size_t)NB * NT * NI / 2];
__device__ __align__(16) uint g_Al [(size_t)NB * NT * NI / 2];
__device__ __align__(16) uint g_Bh1[(size_t)NG * NI / 2];
__device__ __align__(16) uint g_Bl1[(size_t)NG * NI / 2];
__device__ __align__(16) uint g_Bhf[(size_t)NG * ND / 2];
__device__ __align__(16) uint g_Blf[(size_t)NG * ND / 2];
__device__ __align__(16) uint g_Bhb[(size_t)NG * ND / 2];
__device__ __align__(16) uint g_Blb[(size_t)NG * ND / 2];
__device__ unsigned g_bar1;
__device__ unsigned g_bar2;

// ---------------- packed f32x2 helpers ----------------
__device__ __forceinline__ ull pack2(float lo, float hi) {
    ull v; asm("mov.b64 %0, {%1, %2};" : "=l"(v) : "f"(lo), "f"(hi)); return v;
}
__device__ __forceinline__ float2 unpack2(ull v) {
    float lo, hi; asm("mov.b64 {%0, %1}, %2;" : "=f"(lo), "=f"(hi) : "l"(v));
    return make_float2(lo, hi);
}
__device__ __forceinline__ void ffma2(ull& c, ull a, ull b) {
    asm("fma.rn.f32x2 %0, %1, %2, %0;" : "+l"(c) : "l"(a), "l"(b));
}
__device__ __forceinline__ float sigm(float z) { return 1.f / (1.f + __expf(-z)); }

// ---------------- grid-wide spin barrier ----------------
__device__ __forceinline__ void grid_barrier(unsigned* bar, unsigned target) {
    __threadfence();
    __syncthreads();
    if (threadIdx.x == 0) {
        atomicAdd(bar, 1u);
        while (*((volatile unsigned*)bar) < target) { }
        __threadfence();
    }
    __syncthreads();
}

__global__ void reset_bars_kernel() { g_bar1 = 0u; g_bar2 = 0u; }

// ---------------- fp16 split: v -> hi(f16) + lo(f16), packed k-pairs ----------------
__global__ __launch_bounds__(256) void split_fp16_kernel(
    const float* __restrict__ src, uint* __restrict__ hi, uint* __restrict__ lo, int n4)
{
    int i = blockIdx.x * 256 + threadIdx.x;
    if (i >= n4) return;
    float4 v = ((const float4*)src)[i];
    __half hx = __float2half_rn(v.x), hy = __float2half_rn(v.y);
    __half hz = __float2half_rn(v.z), hw = __float2half_rn(v.w);
    __half lx = __float2half_rn(v.x - __half2float(hx));
    __half ly = __float2half_rn(v.y - __half2float(hy));
    __half lz = __float2half_rn(v.z - __half2float(hz));
    __half lw = __float2half_rn(v.w - __half2float(hw));
    __half2 h0 = __halves2half2(hx, hy), h1v = __halves2half2(hz, hw);
    __half2 l0 = __halves2half2(lx, ly), l1v = __halves2half2(lz, lw);
    uint2 ho, lo2;
    ho.x = *(uint*)&h0; ho.y = *(uint*)&h1v;
    lo2.x = *(uint*)&l0; lo2.y = *(uint*)&l1v;
    ((uint2*)hi)[i] = ho;
    ((uint2*)lo)[i] = lo2;
}

// ================= fp16 mma.sync GEMM (3-term split, ~fp32 accurate) =================
// C[M, N=2048] = A[M,K] @ Bt[N,K]^T + bias. CTA tile 128x128, K-chunk 16 (8 uints).
// 8 warps: warp_m = wid&3 (32 rows), warp_n = wid>>2 (64 cols); 2x8 m16n8k16 tiles.

#define KST 12                    // smem row stride in uints (conflict-free frags)
#define GARRU (128 * KST)         // 1536 uints per array
#define GBUFU (4 * GARRU)         // hi/lo x A/B per buffer
#define SMEM_GEMM (2 * GBUFU * 4) // 49152 B

__device__ __forceinline__ void mma_f16(float* d, const uint* a, const uint* b) {
    asm volatile(
        "mma.sync.aligned.m16n8k16.row.col.f32.f16.f16.f32 "
        "{%0,%1,%2,%3}, {%4,%5,%6,%7}, {%8,%9}, {%0,%1,%2,%3};"
        : "+f"(d[0]), "+f"(d[1]), "+f"(d[2]), "+f"(d[3])
        : "r"(a[0]), "r"(a[1]), "r"(a[2]), "r"(a[3]), "r"(b[0]), "r"(b[1]));
}

__global__ __launch_bounds__(256, 1) void gemm_fp16_kernel(
    const uint* __restrict__ Ah, const uint* __restrict__ Al,
    const uint* __restrict__ Bh, const uint* __restrict__ Bl,
    const float* __restrict__ bias, float* __restrict__ C, int K2)
{
    extern __shared__ uint su[];
    const int tid = threadIdx.x;
    const int wid = tid >> 5, lane = tid & 31;
    const int lr = lane >> 2, lc = lane & 3;
    const int warp_m = wid & 3, warp_n = wid >> 2;
    const int n0 = blockIdx.x * 128, m0 = blockIdx.y * 128;

    const int row_s = tid >> 1, half = tid & 1;
    const size_t aoff = (size_t)(m0 + row_s) * K2 + half * 4;
    const size_t boff = (size_t)(n0 + row_s) * K2 + half * 4;
    const uint sidx = row_s * KST + half * 4;

    float acc[2][8][4];
#pragma unroll
    for (int mt = 0; mt < 2; ++mt)
#pragma unroll
        for (int nt = 0; nt < 8; ++nt)
#pragma unroll
            for (int q = 0; q < 4; ++q) acc[mt][nt][q] = 0.f;

    const int nc = K2 >> 3;
    uint4 rAh, rAl, rBh, rBl;

    rAh = *(const uint4*)&Ah[aoff];
    rAl = *(const uint4*)&Al[aoff];
    rBh = *(const uint4*)&Bh[boff];
    rBl = *(const uint4*)&Bl[boff];
    *(uint4*)&su[0 * GARRU + sidx] = rAh;
    *(uint4*)&su[1 * GARRU + sidx] = rAl;
    *(uint4*)&su[2 * GARRU + sidx] = rBh;
    *(uint4*)&su[3 * GARRU + sidx] = rBl;
    __syncthreads();

#pragma unroll 1
    for (int c = 0; c < nc; ++c) {
        const int buf = c & 1;
        if (c + 1 < nc) {
            rAh = *(const uint4*)&Ah[aoff + (c + 1) * 8];
            rAl = *(const uint4*)&Al[aoff + (c + 1) * 8];
            rBh = *(const uint4*)&Bh[boff + (c + 1) * 8];
            rBl = *(const uint4*)&Bl[boff + (c + 1) * 8];
        }
        const uint* sAh = su + buf * GBUFU + 0 * GARRU;
        const uint* sAl = su + buf * GBUFU + 1 * GARRU;
        const uint* sBh = su + buf * GBUFU + 2 * GARRU;
        const uint* sBl = su + buf * GBUFU + 3 * GARRU;

        uint ah[2][4], al[2][4];
#pragma unroll
        for (int mt = 0; mt < 2; ++mt) {
            int row = warp_m * 32 + mt * 16 + lr;
            ah[mt][0] = sAh[row * KST + lc];
            ah[mt][1] = sAh[(row + 8) * KST + lc];
            ah[mt][2] = sAh[row * KST + lc + 4];
            ah[mt][3] = sAh[(row + 8) * KST + lc + 4];
            al[mt][0] = sAl[row * KST + lc];
            al[mt][1] = sAl[(row + 8) * KST + lc];
            al[mt][2] = sAl[row * KST + lc + 4];
            al[mt][3] = sAl[(row + 8) * KST + lc + 4];
        }
        uint bh[8][2], bl[8][2];
#pragma unroll
        for (int nt = 0; nt < 8; ++nt) {
            int n = warp_n * 64 + nt * 8 + lr;
            bh[nt][0] = sBh[n * KST + lc];
            bh[nt][1] = sBh[n * KST + lc + 4];
            bl[nt][0] = sBl[n * KST + lc];
            bl[nt][1] = sBl[n * KST + lc + 4];
        }
#pragma unroll
        for (int mt = 0; mt < 2; ++mt)
#pragma unroll
            for (int nt = 0; nt < 8; ++nt) {
                mma_f16(acc[mt][nt], ah[mt], bh[nt]);
                mma_f16(acc[mt][nt], al[mt], bh[nt]);
                mma_f16(acc[mt][nt], ah[mt], bl[nt]);
            }

        if (c + 1 < nc) {
            const int nb = (c + 1) & 1;
            *(uint4*)&su[nb * GBUFU + 0 * GARRU + sidx] = rAh;
            *(uint4*)&su[nb * GBUFU + 1 * GARRU + sidx] = rAl;
            *(uint4*)&su[nb * GBUFU + 2 * GARRU + sidx] = rBh;
            *(uint4*)&su[nb * GBUFU + 3 * GARRU + sidx] = rBl;
        }
        __syncthreads();
    }

    // epilogue: acc + bias -> C
#pragma unroll
    for (int mt = 0; mt < 2; ++mt) {
        int row = m0 + warp_m * 32 + mt * 16 + lr;
#pragma unroll
        for (int nt = 0; nt < 8; ++nt) {
            int col = n0 + warp_n * 64 + nt * 8 + 2 * lc;
            float2 bv = *(const float2*)&bias[col];
            float2 o0 = make_float2(acc[mt][nt][0] + bv.x, acc[mt][nt][1] + bv.y);
            float2 o1 = make_float2(acc[mt][nt][2] + bv.x, acc[mt][nt][3] + bv.y);
            *(float2*)&C[(size_t)row * NG + col] = o0;
            *(float2*)&C[(size_t)(row + 8) * NG + col] = o1;
        }
    }
}

// ---------------- weight transpose: Wt[n][k] = W[k][n] ----------------
__global__ __launch_bounds__(256) void transpose_kernel(
    const float* __restrict__ W, float* __restrict__ Wt, int K, int N)
{
    __shared__ float t[32][33];
    const int tx = threadIdx.x & 31, ty = threadIdx.x >> 5;
    const int n0 = blockIdx.x << 5, k0 = blockIdx.y << 5;
#pragma unroll
    for (int i = 0; i < 32; i += 8)
        t[ty + i][tx] = W[(size_t)(k0 + ty + i) * N + n0 + tx];
    __syncthreads();
#pragma unroll
    for (int i = 0; i < 32; i += 8)
        Wt[(size_t)(n0 + ty + i) * K + k0 + tx] = t[tx][ty + i];
}

// ================= LSTM recurrence (unchanged from R6 passing version) =================
__device__ __forceinline__ void load_U_shared(float* Us, const float* __restrict__ U,
                                              int u0, int tid) {
    for (int idx = tid; idx < 8192; idx += 256) {
        int k = idx >> 4, r = idx & 15;
        int u = r >> 2, g = r & 3;
        Us[idx] = U[(size_t)k * NG + (size_t)g * ND + u0 + u];
    }
}

__device__ __forceinline__ void stage_ld(float4* r, const float* __restrict__ ht,
                                         int t, int c, int tid) {
    const float4* src = (const float4*)(ht + ((size_t)t * ND + c * 64) * NB);
#pragma unroll
    for (int j = 0; j < 4; ++j) r[j] = src[j * 256 + tid];
}

__device__ __forceinline__ void stage_st(float* dst, const float4* r, int tid) {
#pragma unroll
    for (int j = 0; j < 4; ++j) {
        int flat = j * 256 + tid;
        int kl = flat >> 4, b4 = (flat & 15) << 2;
        *(float4*)&dst[kl * 64 + b4] = r[j];
    }
}

__device__ __forceinline__ void compute_chunk(const float* hs, const float* Us,
                                              int c, int ke, int b2, ull* acc) {
#pragma unroll
    for (int ii = 0; ii < 8; ++ii) {
        int kl = ii * 8 + ke;
        float2 hv = *(const float2*)&hs[kl * 64 + (b2 << 1)];
        ull a0 = pack2(hv.x, hv.x);
        ull a1 = pack2(hv.y, hv.y);
        const ulonglong2* uvp = (const ulonglong2*)&Us[(((c << 6) + kl) << 4)];
#pragma unroll
        for (int u = 0; u < 4; ++u) {
            ulonglong2 uv = uvp[u];
            ffma2(acc[(0 * 4 + u) * 2 + 0], a0, uv.x);
            ffma2(acc[(0 * 4 + u) * 2 + 1], a0, uv.y);
            ffma2(acc[(1 * 4 + u) * 2 + 0], a1, uv.x);
            ffma2(acc[(1 * 4 + u) * 2 + 1], a1, uv.y);
        }
    }
}

__device__ __forceinline__ void accum(const float* __restrict__ ht, int t,
                                      const float* Us, float* h0, float* h1b,
                                      int tid, int ke, int b2, ull* acc) {
    float4 r[4];
    stage_ld(r, ht, t, 0, tid);
    stage_st(h0, r, tid);
    __syncthreads();
#pragma unroll 1
    for (int c = 0; c < 8; ++c) {
        const float* cur = (c & 1) ? h1b : h0;
        float* nxt = (c & 1) ? h0 : h1b;
        if (c < 7) stage_ld(r, ht, t, c + 1, tid);
        compute_chunk(cur, Us, c, ke, b2, acc);
        if (c < 7) stage_st(nxt, r, tid);
        __syncthreads();
    }
}

__device__ __forceinline__ void stage_zs(float* zs, const float* __restrict__ xw,
                                         int t, int u0, int tid) {
    int bb = tid >> 2, g = tid & 3;
    float4 xv = *(const float4*)&xw[((size_t)bb * NT + t) * NG + (size_t)g * ND + u0];
    *(float4*)&zs[bb * 20 + (g << 2)] = xv;
}

__device__ __forceinline__ void gate(float* __restrict__ h_btu, float* __restrict__ h_tub,
                                     int t, int u0, const ull* acc, float& cst,
                                     const float* zs, float* scr, float* shs,
                                     int tid, int ke, int b2, int gb, int gu) {
    ull* scr_u = (ull*)scr;
#pragma unroll
    for (int bb = 0; bb < 2; ++bb)
#pragma unroll
        for (int u = 0; u < 4; ++u)
#pragma unroll
            for (int p = 0; p < 2; ++p)
                scr_u[(size_t)(((b2 << 1) | bb) * 66 + (ke << 3) + (u << 1) + p)] =
                    acc[(bb * 4 + u) * 2 + p];
    __syncthreads();

    float4 z = make_float4(0.f, 0.f, 0.f, 0.f);
#pragma unroll
    for (int k = 0; k < 8; ++k) {
        float4 part = *(const float4*)&scr[gb * 132 + (k << 4) + (gu << 2)];
        z.x += part.x; z.y += part.y; z.z += part.z; z.w += part.w;
    }
    float zi = z.x + zs[gb * 20 + gu];
    float zf = z.y + zs[gb * 20 + 4 + gu];
    float zg = z.z + zs[gb * 20 + 8 + gu];
    float zo = z.w + zs[gb * 20 + 12 + gu];
    float ig = sigm(zi), fg = sigm(zf);
    float gv = fmaxf(zg, 0.f), og = sigm(zo);
    cst = fmaf(fg, cst, ig * gv);
    float h = og * fmaxf(cst, 0.f);

    h_tub[((size_t)t * ND + u0 + gu) * NB + gb] = h;
    shs[(gb << 2) + gu] = h;
    __syncthreads();
    if (tid < 64) {
        float4 h4 = *(const float4*)&shs[tid << 2];
        *(float4*)&h_btu[((size_t)tid * NT + t) * ND + u0] = h4;
    }
}

#define SMEM_L1 (26368 * 4)

__global__ __launch_bounds__(256) void lstm1_kernel(const float* __restrict__ U)
{
    extern __shared__ float sm[];
    float* Us  = sm;
    float* hA  = sm + 8192;
    float* hB  = sm + 12288;
    float* zs  = sm + 16384;
    float* scr = sm + 17664;
    float* shs = sm + 26112;

    const int tid = threadIdx.x;
    const int ke = tid >> 5, b2 = tid & 31;
    const int gb = tid & 63, gu = tid >> 6;
    const int u0 = blockIdx.x << 2;

    load_U_shared(Us, U, u0, tid);
    __syncthreads();

    float cst = 0.f;
    for (int t = 0; t < NT; ++t) {
        stage_zs(zs, g_xw1, t, u0, tid);
        ull acc16[16];
#pragma unroll
        for (int i = 0; i < 16; ++i) acc16[i] = 0ull;
        if (t > 0) {
            grid_barrier(&g_bar1, (unsigned)t * NCTA);
            accum(g_h1t, t - 1, Us, hA, hB, tid, ke, b2, acc16);
        } else {
            __syncthreads();
        }
        gate(g_h1, g_h1t, t, u0, acc16, cst, zs, scr, shs, tid, ke, b2, gb, gu);
    }
}

#define SMEM_FB (35840 * 4)

__global__ __launch_bounds__(256) void lstmfb_kernel(
    const float* __restrict__ Uf, const float* __restrict__ Ub)
{
    extern __shared__ float sm[];
    float* Ufs = sm;
    float* Ubs = sm + 8192;
    float* hA  = sm + 16384;
    float* hB  = sm + 20480;
    float* zsf = sm + 24576;
    float* zsb = sm + 25856;
    float* scr = sm + 27136;
    float* shs = sm + 35584;

    const int tid = threadIdx.x;
    const int ke = tid >> 5, b2 = tid & 31;
    const int gb = tid & 63, gu = tid >> 6;
    const int u0 = blockIdx.x << 2;

    load_U_shared(Ufs, Uf, u0, tid);
    load_U_shared(Ubs, Ub, u0, tid);
    __syncthreads();

    float cf = 0.f, cb = 0.f;
    for (int s = 0; s < NT; ++s) {
        int tf = s, tb = NT - 1 - s;
        stage_zs(zsf, g_xwf, tf, u0, tid);
        stage_zs(zsb, g_xwb, tb, u0, tid);
        ull af[16], ab[16];
#pragma unroll
        for (int i = 0; i < 16; ++i) { af[i] = 0ull; ab[i] = 0ull; }
        if (s > 0) {
            grid_barrier(&g_bar2, (unsigned)s * NCTA);
            accum(g_hft, tf - 1, Ufs, hA, hB, tid, ke, b2, af);
            gate(g_hf, g_hft, tf, u0, af, cf, zsf, scr, shs, tid, ke, b2, gb, gu);
            accum(g_hbt, tb + 1, Ubs, hA, hB, tid, ke, b2, ab);
            gate(g_hb, g_hbt, tb, u0, ab, cb, zsb, scr, shs, tid, ke, b2, gb, gu);
        } else {
            __syncthreads();
            gate(g_hf, g_hft, tf, u0, af, cf, zsf, scr, shs, tid, ke, b2, gb, gu);
            gate(g_hb, g_hbt, tb, u0, ab, cb, zsb, scr, shs, tid, ke, b2, gb, gu);
        }
    }
}

// ---------------- LayerNorm + residual ----------------
__global__ __launch_bounds__(256) void ln_kernel(
    const float* __restrict__ x, const float* __restrict__ gamma,
    const float* __restrict__ beta, float* __restrict__ out)
{
    __shared__ float red[16];
    __shared__ float s_mu, s_rs;
    const int r = blockIdx.x;
    const int tid = threadIdx.x;

    float4 v;
    if (tid < 128) v = *(const float4*)&g_hf[(size_t)r * ND + (tid << 2)];
    else           v = *(const float4*)&g_hb[(size_t)r * ND + ((tid - 128) << 2)];

    float s = v.x + v.y + v.z + v.w;
    float q = v.x * v.x + v.y * v.y + v.z * v.z + v.w * v.w;
#pragma unroll
    for (int o = 16; o; o >>= 1) {
        s += __shfl_down_sync(0xffffffffu, s, o);
        q += __shfl_down_sync(0xffffffffu, q, o);
    }
    if ((tid & 31) == 0) { red[tid >> 5] = s; red[8 + (tid >> 5)] = q; }
    __syncthreads();
    if (tid == 0) {
        float S = 0.f, Q = 0.f;
#pragma unroll
        for (int i = 0; i < 8; ++i) { S += red[i]; Q += red[8 + i]; }
        float mu = S * (1.f / 1024.f);
        float var = Q * (1.f / 1024.f) - mu * mu;
        s_mu = mu;
        s_rs = rsqrtf(var + 1e-6f);
    }
    __syncthreads();
    float mu = s_mu, rs = s_rs;
    int col = tid << 2;
    float4 g4 = *(const float4*)&gamma[col];
    float4 b4 = *(const float4*)&beta[col];
    float4 xv = *(const float4*)&x[(size_t)r * NI + col];
    float4 o;
    o.x = xv.x + (v.x - mu) * rs * g4.x + b4.x;
    o.y = xv.y + (v.y - mu) * rs * g4.y + b4.y;
    o.z = xv.z + (v.z - mu) * rs * g4.z + b4.z;
    o.w = xv.w + (v.w - mu) * rs * g4.w + b4.w;
    *(float4*)&out[(size_t)r * NI + col] = o;
}

// ---------------- host launch ----------------
extern "C" void kernel_launch(void* const* d_in, const int* in_sizes, int n_in,
                              void* d_out, int out_size)
{
    const float* x     = (const float*)d_in[0];
    const float* W1    = (const float*)d_in[1];
    const float* U1    = (const float*)d_in[2];
    const float* b1    = (const float*)d_in[3];
    const float* Wf    = (const float*)d_in[4];
    const float* Uf    = (const float*)d_in[5];
    const float* bf    = (const float*)d_in[6];
    const float* Wb    = (const float*)d_in[7];
    const float* Ub    = (const float*)d_in[8];
    const float* bb    = (const float*)d_in[9];
    const float* gamma = (const float*)d_in[10];
    const float* beta  = (const float*)d_in[11];
    float* out = (float*)d_out;

    void *p_xw1, *p_xwf, *p_xwb, *p_h1, *p_Wt1, *p_Wtf, *p_Wtb;
    void *p_Ah, *p_Al, *p_Bh1, *p_Bl1, *p_Bhf, *p_Blf, *p_Bhb, *p_Blb;
    cudaGetSymbolAddress(&p_xw1, g_xw1);
    cudaGetSymbolAddress(&p_xwf, g_xwf);
    cudaGetSymbolAddress(&p_xwb, g_xwb);
    cudaGetSymbolAddress(&p_h1,  g_h1);
    cudaGetSymbolAddress(&p_Wt1, g_Wt1);
    cudaGetSymbolAddress(&p_Wtf, g_Wtf);
    cudaGetSymbolAddress(&p_Wtb, g_Wtb);
    cudaGetSymbolAddress(&p_Ah,  g_Ah);
    cudaGetSymbolAddress(&p_Al,  g_Al);
    cudaGetSymbolAddress(&p_Bh1, g_Bh1);
    cudaGetSymbolAddress(&p_Bl1, g_Bl1);
    cudaGetSymbolAddress(&p_Bhf, g_Bhf);
    cudaGetSymbolAddress(&p_Blf, g_Blf);
    cudaGetSymbolAddress(&p_Bhb, g_Bhb);
    cudaGetSymbolAddress(&p_Blb, g_Blb);

    cudaFuncSetAttribute(lstm1_kernel,  cudaFuncAttributeMaxDynamicSharedMemorySize, SMEM_L1);
    cudaFuncSetAttribute(lstmfb_kernel, cudaFuncAttributeMaxDynamicSharedMemorySize, SMEM_FB);
    cudaFuncSetAttribute(gemm_fp16_kernel, cudaFuncAttributeMaxDynamicSharedMemorySize, SMEM_GEMM);

    const int M = NB * NT;
    dim3 gg(NG / 128, M / 128);   // n-fast -> A-slice L2 reuse

    reset_bars_kernel<<<1, 1>>>();
    transpose_kernel<<<dim3(NG / 32, NI / 32), 256>>>(W1, (float*)p_Wt1, NI, NG);
    transpose_kernel<<<dim3(NG / 32, ND / 32), 256>>>(Wf, (float*)p_Wtf, ND, NG);
    transpose_kernel<<<dim3(NG / 32, ND / 32), 256>>>(Wb, (float*)p_Wtb, ND, NG);

    // split weights + x into fp16 hi/lo
    {
        int n4 = NG * NI / 4;
        split_fp16_kernel<<<(n4 + 255) / 256, 256>>>((const float*)p_Wt1, (uint*)p_Bh1, (uint*)p_Bl1, n4);
        n4 = NG * ND / 4;
        split_fp16_kernel<<<(n4 + 255) / 256, 256>>>((const float*)p_Wtf, (uint*)p_Bhf, (uint*)p_Blf, n4);
        split_fp16_kernel<<<(n4 + 255) / 256, 256>>>((const float*)p_Wtb, (uint*)p_Bhb, (uint*)p_Blb, n4);
        n4 = M * NI / 4;
        split_fp16_kernel<<<(n4 + 255) / 256, 256>>>(x, (uint*)p_Ah, (uint*)p_Al, n4);
    }

    gemm_fp16_kernel<<<gg, 256, SMEM_GEMM>>>((const uint*)p_Ah, (const uint*)p_Al,
                                             (const uint*)p_Bh1, (const uint*)p_Bl1,
                                             b1, (float*)p_xw1, NI / 2);
    lstm1_kernel<<<NCTA, 256, SMEM_L1>>>(U1);

    {
        int n4 = M * ND / 4;
        split_fp16_kernel<<<(n4 + 255) / 256, 256>>>((const float*)p_h1, (uint*)p_Ah, (uint*)p_Al, n4);
    }
    gemm_fp16_kernel<<<gg, 256, SMEM_GEMM>>>((const uint*)p_Ah, (const uint*)p_Al,
                                             (const uint*)p_Bhf, (const uint*)p_Blf,
                                             bf, (float*)p_xwf, ND / 2);
    gemm_fp16_kernel<<<gg, 256, SMEM_GEMM>>>((const uint*)p_Ah, (const uint*)p_Al,
                                             (const uint*)p_Bhb, (const uint*)p_Blb,
                                             bb, (float*)p_xwb, ND / 2);
    lstmfb_kernel<<<NCTA, 256, SMEM_FB>>>(Uf, Ub);
    ln_kernel<<<M, 256>>>(x, gamma, beta, out);
}